// round 1
// baseline (speedup 1.0000x reference)
#include <cuda_runtime.h>
#include <cuda_bf16.h>
#include <math.h>

// Problem constants
#define BATCH 4
#define TSEQ  2048
#define DMODEL 1024
#define DH    128
#define NTOK  (BATCH * TSEQ)      // 8192
#define SCALE 0.03125f            // 1/sqrt(1024)
#define LOG2E 1.4426950408889634f

// Scratch: Q (rotated), K (rotated), V.  [8192, 128] f32 each = 4 MB each.
__device__ float g_Q[NTOK * DH];
__device__ float g_K[NTOK * DH];
__device__ float g_V[NTOK * DH];

// ---------------------------------------------------------------------------
// Kernel 1: fused QKV projection + RoPE.
// Grid: 256 blocks, each does 32 token rows x all 128 head dims x 3 matrices.
// Block: (128, 4) = 512 threads. threadIdx.x = head dim h, threadIdx.y picks
// token phase; each thread accumulates 8 tokens per projection.
// ---------------------------------------------------------------------------
__global__ __launch_bounds__(512) void qkv_rope_kernel(
    const float* __restrict__ x,
    const float* __restrict__ Wq,
    const float* __restrict__ Wk,
    const float* __restrict__ Wv,
    const float* __restrict__ theta)
{
    __shared__ float sX[32 * 17];          // 32 tokens x 16 k, pad 17
    __shared__ float sW[3][128 * 17];      // 128 h x 16 k, pad 17

    const int h   = threadIdx.x;           // 0..127
    const int ty  = threadIdx.y;           // 0..3
    const int tid = ty * 128 + h;
    const int t0  = blockIdx.x * 32;       // first flat token of this block

    float aq[8], ak[8], av[8];
#pragma unroll
    for (int j = 0; j < 8; j++) { aq[j] = 0.f; ak[j] = 0.f; av[j] = 0.f; }

    for (int kc = 0; kc < DMODEL; kc += 16) {
        __syncthreads();
        // x tile: 32 x 16
        for (int idx = tid; idx < 32 * 16; idx += 512) {
            int tt = idx >> 4, kk = idx & 15;
            sX[tt * 17 + kk] = x[(size_t)(t0 + tt) * DMODEL + kc + kk];
        }
        // weight tiles: 128 x 16 each
        for (int idx = tid; idx < 128 * 16; idx += 512) {
            int hh = idx >> 4, kk = idx & 15;
            sW[0][hh * 17 + kk] = Wq[hh * DMODEL + kc + kk];
            sW[1][hh * 17 + kk] = Wk[hh * DMODEL + kc + kk];
            sW[2][hh * 17 + kk] = Wv[hh * DMODEL + kc + kk];
        }
        __syncthreads();

#pragma unroll
        for (int k = 0; k < 16; k++) {
            float wq = sW[0][h * 17 + k];
            float wk = sW[1][h * 17 + k];
            float wv = sW[2][h * 17 + k];
#pragma unroll
            for (int j = 0; j < 8; j++) {
                float xv = sX[(ty + 4 * j) * 17 + k];
                aq[j] += xv * wq;
                ak[j] += xv * wk;
                av[j] += xv * wv;
            }
        }
    }

    // RoPE on Q and K.  theta repeated in pairs, so theta[h] is correct for
    // both pair elements.  Pair partner sits in adjacent lane (h, h^1).
    const float th   = theta[h];
    const float sign = (h & 1) ? -1.f : 1.f;

#pragma unroll
    for (int j = 0; j < 8; j++) {
        int tt = ty + 4 * j;
        int gt = t0 + tt;                 // flat token 0..8191
        int pos = (gt & (TSEQ - 1)) + 1;  // position within sequence, 1-based
        float ang = (float)pos * th;
        float sn, cs;
        sincosf(ang, &sn, &cs);
        float pq = __shfl_xor_sync(0xffffffffu, aq[j], 1);
        float pk = __shfl_xor_sync(0xffffffffu, ak[j], 1);
        g_Q[(size_t)gt * DH + h] = aq[j] * cs + sign * pq * sn;
        g_K[(size_t)gt * DH + h] = ak[j] * cs + sign * pk * sn;
        g_V[(size_t)gt * DH + h] = av[j];
    }
}

// ---------------------------------------------------------------------------
// Kernel 2: causal flash attention.
// M = N = 32.  64 query tiles per batch; block (pair scheduling) processes
// qtile = blockIdx.x and qtile = 63 - blockIdx.x so every block does ~65
// key-tiles -> balanced single wave of 128 blocks.
// Block: 128 threads. thread = ql*4 + c; ql = query in tile, c = 32-dim slice.
// ---------------------------------------------------------------------------
__global__ __launch_bounds__(128) void attn_kernel(float* __restrict__ out)
{
    __shared__ float sK[32 * DH];
    __shared__ float sV[32 * DH];
    const float4* sK4 = (const float4*)sK;
    const float4* sV4 = (const float4*)sV;

    const int tid = threadIdx.x;
    const int ql  = tid >> 2;     // 0..31
    const int c   = tid & 3;      // 0..3, owns dims [c*32, c*32+32)
    const int b   = blockIdx.y;

    for (int pass = 0; pass < 2; pass++) {
        const int qt = pass ? (63 - (int)blockIdx.x) : (int)blockIdx.x;
        const int qg = qt * 32 + ql;                // query index in sequence
        const size_t row = (size_t)b * TSEQ + qg;   // flat token row

        // Load q slice (pre-scaled by 1/sqrt(D))
        float qr[32];
        {
            const float4* Q4 = (const float4*)(g_Q + row * DH + c * 32);
#pragma unroll
            for (int u = 0; u < 8; u++) {
                float4 v = Q4[u];
                qr[4 * u + 0] = v.x * SCALE;
                qr[4 * u + 1] = v.y * SCALE;
                qr[4 * u + 2] = v.z * SCALE;
                qr[4 * u + 3] = v.w * SCALE;
            }
        }

        float acc[32];
#pragma unroll
        for (int i = 0; i < 32; i++) acc[i] = 0.f;
        float m = -1e30f, l = 0.f;

        const int nkt = qt + 1;   // key tiles 0..qt
        for (int kt = 0; kt < nkt; kt++) {
            const int ks = kt * 32;
            __syncthreads();
            {
                const float4* Kg4 = (const float4*)(g_K + ((size_t)b * TSEQ + ks) * DH);
                const float4* Vg4 = (const float4*)(g_V + ((size_t)b * TSEQ + ks) * DH);
                float4* sK4w = (float4*)sK;
                float4* sV4w = (float4*)sV;
#pragma unroll
                for (int r = 0; r < 8; r++) {       // 1024 float4 per matrix / 128 thr
                    int idx = tid + 128 * r;
                    sK4w[idx] = Kg4[idx];
                    sV4w[idx] = Vg4[idx];
                }
            }
            __syncthreads();

            // Scores for 32 keys (phase-rotated float4 reads: conflict-free)
            float s_arr[32];
#pragma unroll
            for (int j = 0; j < 32; j++) {
                float s = 0.f;
#pragma unroll
                for (int u = 0; u < 8; u++) {
                    int ch = (u + c) & 7;
                    float4 kv = sK4[j * 32 + c * 8 + ch];
                    s += qr[ch * 4 + 0] * kv.x + qr[ch * 4 + 1] * kv.y
                       + qr[ch * 4 + 2] * kv.z + qr[ch * 4 + 3] * kv.w;
                }
                s += __shfl_xor_sync(0xffffffffu, s, 1);
                s += __shfl_xor_sync(0xffffffffu, s, 2);
                if (ks + j > qg) s = -1e30f;        // causal mask
                s_arr[j] = s;
            }

            float tmax = -1e30f;
#pragma unroll
            for (int j = 0; j < 32; j++) tmax = fmaxf(tmax, s_arr[j]);
            float mnew  = fmaxf(m, tmax);
            float alpha = exp2f((m - mnew) * LOG2E);
            l *= alpha;
#pragma unroll
            for (int i = 0; i < 32; i++) acc[i] *= alpha;

#pragma unroll
            for (int j = 0; j < 32; j++) {
                float p = exp2f((s_arr[j] - mnew) * LOG2E);
                l += p;
#pragma unroll
                for (int u = 0; u < 8; u++) {
                    int ch = (u + c) & 7;
                    float4 vv = sV4[j * 32 + c * 8 + ch];
                    acc[ch * 4 + 0] += p * vv.x;
                    acc[ch * 4 + 1] += p * vv.y;
                    acc[ch * 4 + 2] += p * vv.z;
                    acc[ch * 4 + 3] += p * vv.w;
                }
            }
            m = mnew;
        }

        const float inv = 1.f / l;
        float4* O4 = (float4*)(out + row * DH + c * 32);
#pragma unroll
        for (int u = 0; u < 8; u++) {
            float4 o;
            o.x = acc[4 * u + 0] * inv;
            o.y = acc[4 * u + 1] * inv;
            o.z = acc[4 * u + 2] * inv;
            o.w = acc[4 * u + 3] * inv;
            O4[u] = o;
        }
        __syncthreads();   // protect smem before next pass overwrites
    }
}

// ---------------------------------------------------------------------------
extern "C" void kernel_launch(void* const* d_in, const int* in_sizes, int n_in,
                              void* d_out, int out_size)
{
    const float* x     = (const float*)d_in[0];
    const float* Wq    = (const float*)d_in[1];
    const float* Wk    = (const float*)d_in[2];
    const float* Wv    = (const float*)d_in[3];
    const float* theta = (const float*)d_in[4];
    float* out = (float*)d_out;

    dim3 b1(128, 4);
    qkv_rope_kernel<<<NTOK / 32, b1>>>(x, Wq, Wk, Wv, theta);

    dim3 g2(32, BATCH);   // 32 pair-blocks x 4 batches = 128 blocks
    attn_kernel<<<g2, 128>>>(out);
}

// round 2
// speedup vs baseline: 1.3858x; 1.3858x over previous
#include <cuda_runtime.h>
#include <cuda_bf16.h>
#include <math.h>

// Problem constants
#define BATCH 4
#define TSEQ  2048
#define DMODEL 1024
#define DH    128
#define NTOK  (BATCH * TSEQ)      // 8192
#define SCALE 0.03125f            // 1/sqrt(1024)
#define LOG2E 1.4426950408889634f

// Scratch: Q (rotated), K (rotated), V.  [8192, 128] f32 each = 4 MB each.
__device__ float g_Q[NTOK * DH];
__device__ float g_K[NTOK * DH];
__device__ float g_V[NTOK * DH];

// ---------------------------------------------------------------------------
// Kernel 1: fused QKV projection + RoPE.
// Grid: 256 blocks, each does 32 token rows x all 128 head dims x 3 matrices.
// Block: (128, 4) = 512 threads. threadIdx.x = head dim h, threadIdx.y picks
// token phase; each thread accumulates 8 tokens per projection.
// ---------------------------------------------------------------------------
__global__ __launch_bounds__(512) void qkv_rope_kernel(
    const float* __restrict__ x,
    const float* __restrict__ Wq,
    const float* __restrict__ Wk,
    const float* __restrict__ Wv,
    const float* __restrict__ theta)
{
    __shared__ float sX[32 * 17];          // 32 tokens x 16 k, pad 17
    __shared__ float sW[3][128 * 17];      // 128 h x 16 k, pad 17

    const int h   = threadIdx.x;           // 0..127
    const int ty  = threadIdx.y;           // 0..3
    const int tid = ty * 128 + h;
    const int t0  = blockIdx.x * 32;       // first flat token of this block

    float aq[8], ak[8], av[8];
#pragma unroll
    for (int j = 0; j < 8; j++) { aq[j] = 0.f; ak[j] = 0.f; av[j] = 0.f; }

    for (int kc = 0; kc < DMODEL; kc += 16) {
        __syncthreads();
        // x tile: 32 x 16
        for (int idx = tid; idx < 32 * 16; idx += 512) {
            int tt = idx >> 4, kk = idx & 15;
            sX[tt * 17 + kk] = x[(size_t)(t0 + tt) * DMODEL + kc + kk];
        }
        // weight tiles: 128 x 16 each
        for (int idx = tid; idx < 128 * 16; idx += 512) {
            int hh = idx >> 4, kk = idx & 15;
            sW[0][hh * 17 + kk] = Wq[hh * DMODEL + kc + kk];
            sW[1][hh * 17 + kk] = Wk[hh * DMODEL + kc + kk];
            sW[2][hh * 17 + kk] = Wv[hh * DMODEL + kc + kk];
        }
        __syncthreads();

#pragma unroll
        for (int k = 0; k < 16; k++) {
            float wq = sW[0][h * 17 + k];
            float wk = sW[1][h * 17 + k];
            float wv = sW[2][h * 17 + k];
#pragma unroll
            for (int j = 0; j < 8; j++) {
                float xv = sX[(ty + 4 * j) * 17 + k];
                aq[j] += xv * wq;
                ak[j] += xv * wk;
                av[j] += xv * wv;
            }
        }
    }

    // RoPE on Q and K.  theta repeated in pairs, so theta[h] is correct for
    // both pair elements.  Pair partner sits in adjacent lane (h, h^1).
    const float th   = theta[h];
    const float sign = (h & 1) ? -1.f : 1.f;

#pragma unroll
    for (int j = 0; j < 8; j++) {
        int tt = ty + 4 * j;
        int gt = t0 + tt;                 // flat token 0..8191
        int pos = (gt & (TSEQ - 1)) + 1;  // position within sequence, 1-based
        float ang = (float)pos * th;
        float sn, cs;
        sincosf(ang, &sn, &cs);
        float pq = __shfl_xor_sync(0xffffffffu, aq[j], 1);
        float pk = __shfl_xor_sync(0xffffffffu, ak[j], 1);
        g_Q[(size_t)gt * DH + h] = aq[j] * cs + sign * pq * sn;
        g_K[(size_t)gt * DH + h] = ak[j] * cs + sign * pk * sn;
        g_V[(size_t)gt * DH + h] = av[j];
    }
}

// ---------------------------------------------------------------------------
// Kernel 2: causal flash attention.
// M = N = 32.  64 query tiles per batch; block (pair scheduling) processes
// qtile = blockIdx.x and qtile = 63 - blockIdx.x so every block does ~65
// key-tiles -> balanced single wave of 128 blocks.
// Block: 128 threads. thread = ql*4 + c; ql = query in tile, c = 32-dim slice.
// ---------------------------------------------------------------------------
__global__ __launch_bounds__(128) void attn_kernel(float* __restrict__ out)
{
    __shared__ float sK[32 * DH];
    __shared__ float sV[32 * DH];
    const float4* sK4 = (const float4*)sK;
    const float4* sV4 = (const float4*)sV;

    const int tid = threadIdx.x;
    const int ql  = tid >> 2;     // 0..31
    const int c   = tid & 3;      // 0..3, owns dims [c*32, c*32+32)
    const int b   = blockIdx.y;

    for (int pass = 0; pass < 2; pass++) {
        const int qt = pass ? (63 - (int)blockIdx.x) : (int)blockIdx.x;
        const int qg = qt * 32 + ql;                // query index in sequence
        const size_t row = (size_t)b * TSEQ + qg;   // flat token row

        // Load q slice (pre-scaled by 1/sqrt(D))
        float qr[32];
        {
            const float4* Q4 = (const float4*)(g_Q + row * DH + c * 32);
#pragma unroll
            for (int u = 0; u < 8; u++) {
                float4 v = Q4[u];
                qr[4 * u + 0] = v.x * SCALE;
                qr[4 * u + 1] = v.y * SCALE;
                qr[4 * u + 2] = v.z * SCALE;
                qr[4 * u + 3] = v.w * SCALE;
            }
        }

        float acc[32];
#pragma unroll
        for (int i = 0; i < 32; i++) acc[i] = 0.f;
        float m = -1e30f, l = 0.f;

        const int nkt = qt + 1;   // key tiles 0..qt
        for (int kt = 0; kt < nkt; kt++) {
            const int ks = kt * 32;
            __syncthreads();
            {
                const float4* Kg4 = (const float4*)(g_K + ((size_t)b * TSEQ + ks) * DH);
                const float4* Vg4 = (const float4*)(g_V + ((size_t)b * TSEQ + ks) * DH);
                float4* sK4w = (float4*)sK;
                float4* sV4w = (float4*)sV;
#pragma unroll
                for (int r = 0; r < 8; r++) {       // 1024 float4 per matrix / 128 thr
                    int idx = tid + 128 * r;
                    sK4w[idx] = Kg4[idx];
                    sV4w[idx] = Vg4[idx];
                }
            }
            __syncthreads();

            // Scores for 32 keys (phase-rotated float4 reads: conflict-free)
            float s_arr[32];
#pragma unroll
            for (int j = 0; j < 32; j++) {
                float s = 0.f;
#pragma unroll
                for (int u = 0; u < 8; u++) {
                    int ch = (u + c) & 7;
                    float4 kv = sK4[j * 32 + c * 8 + ch];
                    s += qr[ch * 4 + 0] * kv.x + qr[ch * 4 + 1] * kv.y
                       + qr[ch * 4 + 2] * kv.z + qr[ch * 4 + 3] * kv.w;
                }
                s += __shfl_xor_sync(0xffffffffu, s, 1);
                s += __shfl_xor_sync(0xffffffffu, s, 2);
                if (ks + j > qg) s = -1e30f;        // causal mask
                s_arr[j] = s;
            }

            float tmax = -1e30f;
#pragma unroll
            for (int j = 0; j < 32; j++) tmax = fmaxf(tmax, s_arr[j]);
            float mnew  = fmaxf(m, tmax);
            float alpha = exp2f((m - mnew) * LOG2E);
            l *= alpha;
#pragma unroll
            for (int i = 0; i < 32; i++) acc[i] *= alpha;

#pragma unroll
            for (int j = 0; j < 32; j++) {
                float p = exp2f((s_arr[j] - mnew) * LOG2E);
                l += p;
#pragma unroll
                for (int u = 0; u < 8; u++) {
                    int ch = (u + c) & 7;
                    float4 vv = sV4[j * 32 + c * 8 + ch];
                    acc[ch * 4 + 0] += p * vv.x;
                    acc[ch * 4 + 1] += p * vv.y;
                    acc[ch * 4 + 2] += p * vv.z;
                    acc[ch * 4 + 3] += p * vv.w;
                }
            }
            m = mnew;
        }

        const float inv = 1.f / l;
        float4* O4 = (float4*)(out + row * DH + c * 32);
#pragma unroll
        for (int u = 0; u < 8; u++) {
            float4 o;
            o.x = acc[4 * u + 0] * inv;
            o.y = acc[4 * u + 1] * inv;
            o.z = acc[4 * u + 2] * inv;
            o.w = acc[4 * u + 3] * inv;
            O4[u] = o;
        }
        __syncthreads();   // protect smem before next pass overwrites
    }
}

// ---------------------------------------------------------------------------
extern "C" void kernel_launch(void* const* d_in, const int* in_sizes, int n_in,
                              void* d_out, int out_size)
{
    const float* x     = (const float*)d_in[0];
    const float* Wq    = (const float*)d_in[1];
    const float* Wk    = (const float*)d_in[2];
    const float* Wv    = (const float*)d_in[3];
    const float* theta = (const float*)d_in[4];
    float* out = (float*)d_out;

    dim3 b1(128, 4);
    qkv_rope_kernel<<<NTOK / 32, b1>>>(x, Wq, Wk, Wv, theta);

    dim3 g2(32, BATCH);   // 32 pair-blocks x 4 batches = 128 blocks
    attn_kernel<<<g2, 128>>>(out);
}

// round 3
// speedup vs baseline: 13.0899x; 9.4459x over previous
#include <cuda_runtime.h>
#include <math.h>

#define TSEQ   2048
#define NTOK   8192
#define DM     1024
#define DH     128
#define QSCALE 0.03125f                 // 1/sqrt(1024)
#define LOG2E  1.4426950408889634f

// Q,K stored transposed: [DH][NTOK] (token = b*2048+t). V token-major.
__device__ float g_Qt[DH * NTOK];
__device__ float g_Kt[DH * NTOK];
__device__ float g_V [NTOK * DH];
// split-K partials: [b][qt][chunk][64 q][128 d], m/l in log2 units
__device__ float g_Op[4 * 32 * 4 * 64 * DH];
__device__ float g_m [4 * 32 * 4 * 64];
__device__ float g_l [4 * 32 * 4 * 64];

__device__ __forceinline__ float ex2f(float x) {
    float y; asm("ex2.approx.ftz.f32 %0, %1;" : "=f"(y) : "f"(x)); return y;
}

// ---------------------------------------------------------------------------
// Kernel 1: QKV projection + RoPE.  grid (128 token-tiles, 3 matrices), 256 thr.
// Tile 64M x 128N, frags 4m x 8n with n = tx + 16*j (conflict-free LDS32).
// ---------------------------------------------------------------------------
__global__ __launch_bounds__(256) void qkv_rope(
    const float* __restrict__ x,  const float* __restrict__ Wq,
    const float* __restrict__ Wk, const float* __restrict__ Wv,
    const float* __restrict__ theta)
{
    __shared__ float sX[16][68];    // [k][m]
    __shared__ float sW[16][132];   // [k][n]

    const int tid = threadIdx.x;
    const int tx = tid & 15, ty = tid >> 4;
    const int t0 = blockIdx.x * 64;
    const int mat = blockIdx.y;
    const float* __restrict__ W = (mat == 0) ? Wq : (mat == 1) ? Wk : Wv;

    float acc[4][8];
#pragma unroll
    for (int i = 0; i < 4; i++)
#pragma unroll
        for (int j = 0; j < 8; j++) acc[i][j] = 0.f;

    const int lt = tid >> 2, lk = (tid & 3) * 4;   // x loader
    const int wh = tid >> 1, wk = (tid & 1) * 8;   // W loader

    for (int kc = 0; kc < DM; kc += 16) {
        float4 xv  = *(const float4*)(x + (size_t)(t0 + lt) * DM + kc + lk);
        float4 wv0 = *(const float4*)(W + (size_t)wh * DM + kc + wk);
        float4 wv1 = *(const float4*)(W + (size_t)wh * DM + kc + wk + 4);
        __syncthreads();
        sX[lk + 0][lt] = xv.x;  sX[lk + 1][lt] = xv.y;
        sX[lk + 2][lt] = xv.z;  sX[lk + 3][lt] = xv.w;
        sW[wk + 0][wh] = wv0.x; sW[wk + 1][wh] = wv0.y;
        sW[wk + 2][wh] = wv0.z; sW[wk + 3][wh] = wv0.w;
        sW[wk + 4][wh] = wv1.x; sW[wk + 5][wh] = wv1.y;
        sW[wk + 6][wh] = wv1.z; sW[wk + 7][wh] = wv1.w;
        __syncthreads();
#pragma unroll
        for (int k = 0; k < 16; k++) {
            float4 xf = *(float4*)&sX[k][ty * 4];
            float xr[4] = {xf.x, xf.y, xf.z, xf.w};
            float wr[8];
#pragma unroll
            for (int j = 0; j < 8; j++) wr[j] = sW[k][tx + 16 * j];
#pragma unroll
            for (int i = 0; i < 4; i++)
#pragma unroll
                for (int j = 0; j < 8; j++) acc[i][j] += xr[i] * wr[j];
        }
    }

    if (mat < 2) {
        // RoPE: n = tx + 16*j; pair partner is lane tid^1 (tx^1).
        const float sign = (tx & 1) ? -1.f : 1.f;
#pragma unroll
        for (int i = 0; i < 4; i++) {
            int tok = t0 + ty * 4 + i;
            float pos = (float)((tok & (TSEQ - 1)) + 1);
#pragma unroll
            for (int j = 0; j < 8; j++) {
                int n = tx + 16 * j;
                float sn, cs;
                sincosf(pos * theta[n], &sn, &cs);
                float a = acc[i][j];
                float p = __shfl_xor_sync(0xffffffffu, a, 1);
                acc[i][j] = a * cs + sign * p * sn;
            }
        }
        float sc = (mat == 0) ? (QSCALE * LOG2E) : 1.f;
        float* dst = (mat == 0) ? g_Qt : g_Kt;
#pragma unroll
        for (int j = 0; j < 8; j++) {
            int n = tx + 16 * j;
            float4 v = make_float4(acc[0][j] * sc, acc[1][j] * sc,
                                   acc[2][j] * sc, acc[3][j] * sc);
            *(float4*)(dst + (size_t)n * NTOK + t0 + ty * 4) = v;
        }
    } else {
#pragma unroll
        for (int i = 0; i < 4; i++) {
            int tok = t0 + ty * 4 + i;
#pragma unroll
            for (int j = 0; j < 8; j++)
                g_V[(size_t)tok * DH + tx + 16 * j] = acc[i][j];
        }
    }
}

// ---------------------------------------------------------------------------
// Kernel 2: flash attention partials.  320 blocks x 256 threads.
// Block = (batch, 64-query tile, 512-key chunk).  K-tile N=128.
// Thread: qt_thr = tid/16 owns 4 q rows; lane role tid%16 is kt_thr (scores,
// k = kt + 16*j) and dg (PV, d = dg + 16*u).  All LDS conflict-free.
// ---------------------------------------------------------------------------
__global__ __launch_bounds__(256, 1) void attn_part(int dummy)
{
    extern __shared__ float sm[];
    float* sQ = sm;                    // [128 d][68]  (64 q + pad)
    float* sK = sQ + 128 * 68;         // [128 d][132] (128 k + pad)
    float* sV = sK + 128 * 132;        // [128 t][132] (128 d + pad)
    float* sP = sV + 128 * 132;        // [64 q][132]  (128 k + pad)

    const int tid = threadIdx.x;
    const int qt_thr = tid >> 4;       // 0..15, owns 4 q
    const int lr = tid & 15;           // kt_thr / dg

    // block -> (b, qt, chunk)
    int r = blockIdx.x % 80;
    int b = blockIdx.x / 80;
    int qt, chunk;
    if (r < 8)       { qt = r;                 chunk = 0; }
    else if (r < 24) { qt = 8  + (r - 8) / 2;  chunk = (r - 8) % 2; }
    else if (r < 48) { qt = 16 + (r - 24) / 3; chunk = (r - 24) % 3; }
    else             { qt = 24 + (r - 48) / 4; chunk = (r - 48) % 4; }

    const int q0   = qt * 64;                       // within batch
    const int kbeg = chunk * 512;
    const int kend = min(q0 + 64, kbeg + 512);
    const int tokb = b * TSEQ;

    // load Q tile [128 d][64 q]
    for (int idx = tid; idx < 128 * 16; idx += 256) {
        int row = idx >> 4, c4 = idx & 15;
        float4 v = *(const float4*)(g_Qt + (size_t)row * NTOK + tokb + q0 + c4 * 4);
        *(float4*)&sQ[row * 68 + c4 * 4] = v;
    }

    float O[4][8];
#pragma unroll
    for (int i = 0; i < 4; i++)
#pragma unroll
        for (int u = 0; u < 8; u++) O[i][u] = 0.f;
    float m[4] = {-1e30f, -1e30f, -1e30f, -1e30f};
    float l[4] = {0.f, 0.f, 0.f, 0.f};

    for (int ks = kbeg; ks < kend; ks += 128) {
        __syncthreads();   // prior PV done before overwriting sK/sV
        for (int idx = tid; idx < 128 * 32; idx += 256) {
            int row = idx >> 5, c4 = idx & 31;
            *(float4*)&sK[row * 132 + c4 * 4] =
                *(const float4*)(g_Kt + (size_t)row * NTOK + tokb + ks + c4 * 4);
            *(float4*)&sV[row * 132 + c4 * 4] =
                *(const float4*)(g_V + (size_t)(tokb + ks + row) * DH + c4 * 4);
        }
        __syncthreads();

        // --- scores S[4 q][8 k], k = lr + 16*j ---
        float S[4][8];
#pragma unroll
        for (int i = 0; i < 4; i++)
#pragma unroll
            for (int j = 0; j < 8; j++) S[i][j] = 0.f;
#pragma unroll 8
        for (int d = 0; d < 128; d++) {
            float4 qf = *(float4*)&sQ[d * 68 + qt_thr * 4];
            float qr[4] = {qf.x, qf.y, qf.z, qf.w};
            float kr[8];
#pragma unroll
            for (int j = 0; j < 8; j++) kr[j] = sK[d * 132 + lr + 16 * j];
#pragma unroll
            for (int i = 0; i < 4; i++)
#pragma unroll
                for (int j = 0; j < 8; j++) S[i][j] += qr[i] * kr[j];
        }

        if (ks + 128 > q0) {   // diagonal tile: causal mask
#pragma unroll
            for (int i = 0; i < 4; i++) {
                int qg = q0 + qt_thr * 4 + i;
#pragma unroll
                for (int j = 0; j < 8; j++)
                    if (ks + lr + 16 * j > qg) S[i][j] = -1e30f;
            }
        }

        // --- online softmax (log2 units; Q pre-scaled by 1/sqrt(D)*log2e) ---
#pragma unroll
        for (int i = 0; i < 4; i++) {
            float tmax = S[i][0];
#pragma unroll
            for (int j = 1; j < 8; j++) tmax = fmaxf(tmax, S[i][j]);
#pragma unroll
            for (int o = 1; o < 16; o <<= 1)
                tmax = fmaxf(tmax, __shfl_xor_sync(0xffffffffu, tmax, o));
            float mnew = fmaxf(m[i], tmax);
            float al = ex2f(m[i] - mnew);
            m[i] = mnew;
            float ps = 0.f;
#pragma unroll
            for (int j = 0; j < 8; j++) {
                float p = ex2f(S[i][j] - mnew);
                S[i][j] = p;
                ps += p;
            }
#pragma unroll
            for (int o = 1; o < 16; o <<= 1)
                ps += __shfl_xor_sync(0xffffffffu, ps, o);
            l[i] = l[i] * al + ps;
#pragma unroll
            for (int u = 0; u < 8; u++) O[i][u] *= al;
        }

        // stage P: sP[q][k]
#pragma unroll
        for (int i = 0; i < 4; i++)
#pragma unroll
            for (int j = 0; j < 8; j++)
                sP[(qt_thr * 4 + i) * 132 + lr + 16 * j] = S[i][j];
        __syncthreads();

        // --- PV: O[4 q][8 d], d = lr + 16*u ---
#pragma unroll 4
        for (int k = 0; k < 128; k++) {
            float pv[4];
#pragma unroll
            for (int i = 0; i < 4; i++) pv[i] = sP[(qt_thr * 4 + i) * 132 + k];
            float vr[8];
#pragma unroll
            for (int u = 0; u < 8; u++) vr[u] = sV[k * 132 + lr + 16 * u];
#pragma unroll
            for (int i = 0; i < 4; i++)
#pragma unroll
                for (int u = 0; u < 8; u++) O[i][u] += pv[i] * vr[u];
        }
    }

    // write partials (unnormalized O, m, l)
    const int base = ((b * 32 + qt) * 4 + chunk) * 64;
#pragma unroll
    for (int i = 0; i < 4; i++) {
        int q = qt_thr * 4 + i;
#pragma unroll
        for (int u = 0; u < 8; u++)
            g_Op[(size_t)(base + q) * DH + lr + 16 * u] = O[i][u];
        if (lr == 0) { g_m[base + q] = m[i]; g_l[base + q] = l[i]; }
    }
}

// ---------------------------------------------------------------------------
// Kernel 3: combine chunks + normalize.  grid (32 qt, 4 b), 256 threads.
// ---------------------------------------------------------------------------
__global__ __launch_bounds__(256) void attn_combine(float* __restrict__ out)
{
    const int qt = blockIdx.x, b = blockIdx.y;
    const int tid = threadIdx.x;
    const int q = tid >> 2, d0 = (tid & 3) * 32;
    const int nch = qt / 8 + 1;
    const int base = (b * 32 + qt) * 4 * 64 + q;   // chunk stride = 64

    float mm[4], ww[4];
    float M = -1e30f;
    for (int c = 0; c < nch; c++) { mm[c] = g_m[base + c * 64]; M = fmaxf(M, mm[c]); }
    float L = 0.f;
    for (int c = 0; c < nch; c++) { ww[c] = ex2f(mm[c] - M); L += g_l[base + c * 64] * ww[c]; }
    float inv = 1.f / L;

    float* op = out + (size_t)(b * TSEQ + qt * 64 + q) * DH + d0;
#pragma unroll
    for (int d = 0; d < 32; d += 4) {
        float4 a = make_float4(0.f, 0.f, 0.f, 0.f);
        for (int c = 0; c < nch; c++) {
            float4 v = *(const float4*)(g_Op + (size_t)(base + c * 64) * DH + d0 + d);
            a.x += ww[c] * v.x; a.y += ww[c] * v.y;
            a.z += ww[c] * v.z; a.w += ww[c] * v.w;
        }
        a.x *= inv; a.y *= inv; a.z *= inv; a.w *= inv;
        *(float4*)(op + d) = a;
    }
}

// ---------------------------------------------------------------------------
extern "C" void kernel_launch(void* const* d_in, const int* in_sizes, int n_in,
                              void* d_out, int out_size)
{
    const float* x     = (const float*)d_in[0];
    const float* Wq    = (const float*)d_in[1];
    const float* Wk    = (const float*)d_in[2];
    const float* Wv    = (const float*)d_in[3];
    const float* theta = (const float*)d_in[4];
    float* out = (float*)d_out;

    static const int ATTN_SMEM = (128 * 68 + 128 * 132 + 128 * 132 + 64 * 132) * 4;
    cudaFuncSetAttribute(attn_part, cudaFuncAttributeMaxDynamicSharedMemorySize,
                         ATTN_SMEM);

    dim3 g1(NTOK / 64, 3);
    qkv_rope<<<g1, 256>>>(x, Wq, Wk, Wv, theta);

    attn_part<<<320, 256, ATTN_SMEM>>>(0);

    dim3 g3(32, 4);
    attn_combine<<<g3, 256>>>(out);
}

// round 6
// speedup vs baseline: 24.2119x; 1.8497x over previous
#include <cuda_runtime.h>
#include <cuda_bf16.h>
#include <math.h>
#include <stdint.h>

#define TSEQ   2048
#define NTOK   8192
#define DM     1024
#define DH     128
#define QSCALE 0.03125f                 // 1/sqrt(1024)
#define LOG2E  1.4426950408889634f

// Q,K token-major bf16 hi/lo planes; Vt transposed [DH][NTOK] planes.
__device__ unsigned short g_Qhi[NTOK * DH], g_Qlo[NTOK * DH];
__device__ unsigned short g_Khi[NTOK * DH], g_Klo[NTOK * DH];
__device__ unsigned short g_Vthi[DH * NTOK], g_Vtlo[DH * NTOK];
__device__ float g_ctab[TSEQ * DH];
__device__ float g_stab[TSEQ * DH];
// split-K partials: [b][qt][chunk][64 q][128 d]; m/l in log2 units
__device__ float g_Op[4 * 32 * 4 * 64 * DH];
__device__ float g_m [4 * 32 * 4 * 64];
__device__ float g_l [4 * 32 * 4 * 64];

__device__ __forceinline__ float ex2f(float x) {
    float y; asm("ex2.approx.ftz.f32 %0, %1;" : "=f"(y) : "f"(x)); return y;
}
__device__ __forceinline__ uint32_t s2u(const void* p) {
    uint32_t a;
    asm("{ .reg .u64 t; cvta.to.shared.u64 t, %1; cvt.u32.u64 %0, t; }"
        : "=r"(a) : "l"(p));
    return a;
}
#define CPA16(dst, src) \
    asm volatile("cp.async.cg.shared.global [%0], [%1], 16;" :: "r"(dst), "l"(src) : "memory")
#define CPA_COMMIT() asm volatile("cp.async.commit_group;" ::: "memory")
#define CPA_WAIT0()  asm volatile("cp.async.wait_group 0;" ::: "memory")

// bf16 m16n8k16 HMMA (sm_80 baseline PTX; runs on .target sm_103)
__device__ __forceinline__ void mma16(float* c, const uint32_t* a, const uint32_t* b) {
    asm volatile(
        "mma.sync.aligned.m16n8k16.row.col.f32.bf16.bf16.f32 "
        "{%0,%1,%2,%3}, {%4,%5,%6,%7}, {%8,%9}, {%0,%1,%2,%3};"
        : "+f"(c[0]), "+f"(c[1]), "+f"(c[2]), "+f"(c[3])
        : "r"(a[0]), "r"(a[1]), "r"(a[2]), "r"(a[3]), "r"(b[0]), "r"(b[1]));
}

// split (f0,f1) into packed bf16x2 hi and lo pairs (element k in low half)
__device__ __forceinline__ void split2(float f0, float f1, uint32_t& hi, uint32_t& lo) {
    __nv_bfloat16 h0 = __float2bfloat16(f0);
    __nv_bfloat16 h1 = __float2bfloat16(f1);
    __nv_bfloat16 l0 = __float2bfloat16(f0 - __bfloat162float(h0));
    __nv_bfloat16 l1 = __float2bfloat16(f1 - __bfloat162float(h1));
    hi = (uint32_t)__bfloat16_as_ushort(h0) | ((uint32_t)__bfloat16_as_ushort(h1) << 16);
    lo = (uint32_t)__bfloat16_as_ushort(l0) | ((uint32_t)__bfloat16_as_ushort(l1) << 16);
}

// ---------------------------------------------------------------------------
__global__ __launch_bounds__(128) void rope_table(const float* __restrict__ theta) {
    int p = blockIdx.x, n = threadIdx.x;
    float s, c;
    sincosf((float)(p + 1) * theta[n], &s, &c);
    g_ctab[p * DH + n] = c;
    g_stab[p * DH + n] = s;
}

// ---------------------------------------------------------------------------
// QKV projection, bf16x3 mma.  grid (64 token-tiles, 3 mats), 256 thr (8 warps
// = 4m x 2n).  Tile 128M x 128N, K chunks of 32, reg-prefetched loads.
// smem tiles hold packed bf16x2 K-pairs, row stride 20 u32 (conflict-free).
// ---------------------------------------------------------------------------
#define QS 20

__global__ __launch_bounds__(256, 2)
void qkv_mma(const float* __restrict__ x,  const float* __restrict__ Wq,
             const float* __restrict__ Wk, const float* __restrict__ Wv) {
    __shared__ uint32_t sXhi[128 * QS], sXlo[128 * QS];
    __shared__ uint32_t sWhi[128 * QS], sWlo[128 * QS];

    const int tid = threadIdx.x;
    const int lane = tid & 31, wid = tid >> 5;
    const int warp_m = wid & 3, warp_n = wid >> 2;
    const int m_base = warp_m * 32, n_base = warp_n * 64;
    const int lq4 = lane >> 2, lk = lane & 3;
    const int t0 = blockIdx.x * 128;
    const int mat = blockIdx.y;
    const float* __restrict__ W = (mat == 0) ? Wq : ((mat == 1) ? Wk : Wv);

    const int lrow = tid >> 1, lseg = tid & 1;
    const float* gx = x + (size_t)(t0 + lrow) * DM + lseg * 16;
    const float* gw = W + (size_t)lrow * DM + lseg * 16;

    float4 rx[4], rw[4];
#pragma unroll
    for (int c = 0; c < 4; c++) {
        rx[c] = *(const float4*)(gx + c * 4);
        rw[c] = *(const float4*)(gw + c * 4);
    }

    float acc[2][8][4];
#pragma unroll
    for (int i = 0; i < 2; i++)
#pragma unroll
        for (int j = 0; j < 8; j++)
#pragma unroll
            for (int k = 0; k < 4; k++) acc[i][j][k] = 0.f;

    for (int ci = 0; ci < 32; ci++) {
        __syncthreads();
        {
            uint32_t hp[8], lp[8];
            const int sb = lrow * QS + lseg * 8;
#pragma unroll
            for (int c = 0; c < 4; c++) {
                split2(rx[c].x, rx[c].y, hp[2 * c],     lp[2 * c]);
                split2(rx[c].z, rx[c].w, hp[2 * c + 1], lp[2 * c + 1]);
            }
            *(uint4*)&sXhi[sb]     = make_uint4(hp[0], hp[1], hp[2], hp[3]);
            *(uint4*)&sXhi[sb + 4] = make_uint4(hp[4], hp[5], hp[6], hp[7]);
            *(uint4*)&sXlo[sb]     = make_uint4(lp[0], lp[1], lp[2], lp[3]);
            *(uint4*)&sXlo[sb + 4] = make_uint4(lp[4], lp[5], lp[6], lp[7]);
#pragma unroll
            for (int c = 0; c < 4; c++) {
                split2(rw[c].x, rw[c].y, hp[2 * c],     lp[2 * c]);
                split2(rw[c].z, rw[c].w, hp[2 * c + 1], lp[2 * c + 1]);
            }
            *(uint4*)&sWhi[sb]     = make_uint4(hp[0], hp[1], hp[2], hp[3]);
            *(uint4*)&sWhi[sb + 4] = make_uint4(hp[4], hp[5], hp[6], hp[7]);
            *(uint4*)&sWlo[sb]     = make_uint4(lp[0], lp[1], lp[2], lp[3]);
            *(uint4*)&sWlo[sb + 4] = make_uint4(lp[4], lp[5], lp[6], lp[7]);
        }
        __syncthreads();
        if (ci < 31) {
            const float* gx2 = gx + (ci + 1) * 32;
            const float* gw2 = gw + (ci + 1) * 32;
#pragma unroll
            for (int c = 0; c < 4; c++) {
                rx[c] = *(const float4*)(gx2 + c * 4);
                rw[c] = *(const float4*)(gw2 + c * 4);
            }
        }
#pragma unroll
        for (int kk = 0; kk < 2; kk++) {
            const int base = kk * 8 + lk;
            uint32_t ah[2][4], al[2][4];
#pragma unroll
            for (int mt = 0; mt < 2; mt++) {
                const uint32_t* ph = &sXhi[(m_base + mt * 16 + lq4) * QS];
                const uint32_t* pl = &sXlo[(m_base + mt * 16 + lq4) * QS];
                ah[mt][0] = ph[base];          ah[mt][1] = ph[base + 8 * QS];
                ah[mt][2] = ph[base + 4];      ah[mt][3] = ph[base + 8 * QS + 4];
                al[mt][0] = pl[base];          al[mt][1] = pl[base + 8 * QS];
                al[mt][2] = pl[base + 4];      al[mt][3] = pl[base + 8 * QS + 4];
            }
#pragma unroll
            for (int nt = 0; nt < 8; nt++) {
                const uint32_t* ph = &sWhi[(n_base + nt * 8 + lq4) * QS];
                const uint32_t* pl = &sWlo[(n_base + nt * 8 + lq4) * QS];
                uint32_t bh[2] = {ph[base], ph[base + 4]};
                uint32_t bl[2] = {pl[base], pl[base + 4]};
#pragma unroll
                for (int mt = 0; mt < 2; mt++) {
                    mma16(acc[mt][nt], ah[mt], bh);
                    mma16(acc[mt][nt], ah[mt], bl);
                    mma16(acc[mt][nt], al[mt], bh);
                }
            }
        }
    }

    // ---- epilogue ----
    if (mat < 2) {
        const float sc = (mat == 0) ? (QSCALE * LOG2E) : 1.f;
        unsigned short* dhi = (mat == 0) ? g_Qhi : g_Khi;
        unsigned short* dlo = (mat == 0) ? g_Qlo : g_Klo;
#pragma unroll
        for (int mt = 0; mt < 2; mt++)
#pragma unroll
            for (int h = 0; h < 2; h++) {
                const int tok = t0 + m_base + mt * 16 + lq4 + 8 * h;
                const int pos = tok & (TSEQ - 1);
#pragma unroll
                for (int nt = 0; nt < 8; nt++) {
                    const int colE = n_base + nt * 8 + 2 * lk;
                    float e = acc[mt][nt][2 * h] * sc;
                    float o = acc[mt][nt][2 * h + 1] * sc;
                    float ct = g_ctab[pos * DH + colE];
                    float st = g_stab[pos * DH + colE];
                    float re = e * ct + o * st;
                    float ro = o * ct - e * st;
                    uint32_t hi, lo;
                    split2(re, ro, hi, lo);
                    *(uint32_t*)&dhi[(size_t)tok * DH + colE] = hi;
                    *(uint32_t*)&dlo[(size_t)tok * DH + colE] = lo;
                }
            }
    } else {
#pragma unroll
        for (int mt = 0; mt < 2; mt++)
#pragma unroll
            for (int h = 0; h < 2; h++) {
                const int tok = t0 + m_base + mt * 16 + lq4 + 8 * h;
#pragma unroll
                for (int nt = 0; nt < 8; nt++) {
                    const int colE = n_base + nt * 8 + 2 * lk;
#pragma unroll
                    for (int e = 0; e < 2; e++) {
                        float v = acc[mt][nt][2 * h + e];
                        __nv_bfloat16 hb = __float2bfloat16(v);
                        __nv_bfloat16 lb = __float2bfloat16(v - __bfloat162float(hb));
                        g_Vthi[(size_t)(colE + e) * NTOK + tok] = __bfloat16_as_ushort(hb);
                        g_Vtlo[(size_t)(colE + e) * NTOK + tok] = __bfloat16_as_ushort(lb);
                    }
                }
            }
    }
}

// ---------------------------------------------------------------------------
// Flash attention partials, bf16x3 mma.  320 blocks x 256 threads (8 warps:
// 4m x 2n).  Block = (batch, 64-q tile, 512-key chunk); key tiles of 128.
// smem: packed bf16x2 pair tiles, row stride 68 u32 (conflict-free).
// ---------------------------------------------------------------------------
#define AST 68
#define O_QHI 0
#define O_QLO (O_QHI + 64 * AST)
#define O_KHI (O_QLO + 64 * AST)
#define O_KLO (O_KHI + 128 * AST)
#define O_VHI (O_KLO + 128 * AST)
#define O_VLO (O_VHI + 128 * AST)
#define O_PHI (O_VLO + 128 * AST)
#define O_PLO (O_PHI + 64 * AST)
#define O_F   (O_PLO + 64 * AST)
#define AT_SMEM ((O_F + 384) * 4)

__global__ __launch_bounds__(256, 1) void attn_part(int dummy)
{
    extern __shared__ uint32_t smu[];
    float* sMv = (float*)(smu + O_F);
    float* sLv = sMv + 64;
    float* sRm = sLv + 64;      // [2][64]
    float* sRl = sRm + 128;     // [2][64]
    const uint32_t sb = s2u(smu);

    const int tid = threadIdx.x;
    const int lane = tid & 31, wid = tid >> 5;
    const int warp_m = wid & 3, warp_n = wid >> 2;
    const int m_base = warp_m * 16, n_base = warp_n * 64;
    const int lq4 = lane >> 2, lk = lane & 3;

    // block -> (b, qt, chunk)
    int r = blockIdx.x % 80;
    int b = blockIdx.x / 80;
    int qt, chunk;
    if (r < 8)       { qt = r;                 chunk = 0; }
    else if (r < 24) { qt = 8  + (r - 8) / 2;  chunk = (r - 8) % 2; }
    else if (r < 48) { qt = 16 + (r - 24) / 3; chunk = (r - 24) % 3; }
    else             { qt = 24 + (r - 48) / 4; chunk = (r - 48) % 4; }

    const int q0   = qt * 64;
    const int kbeg = chunk * 512;
    const int kend = min(q0 + 64, kbeg + 512);
    const int tokb = b * TSEQ;

    // Q planes: 64 rows x 16 cp16 each
#pragma unroll
    for (int it = 0; it < 4; it++) {
        int idx = tid + 256 * it;
        int row = idx >> 4, c = idx & 15;
        CPA16(sb + (O_QHI + row * AST + c * 4) * 4,
              (const char*)g_Qhi + ((size_t)(tokb + q0 + row) * DH + c * 8) * 2);
        CPA16(sb + (O_QLO + row * AST + c * 4) * 4,
              (const char*)g_Qlo + ((size_t)(tokb + q0 + row) * DH + c * 8) * 2);
    }
    CPA_COMMIT();
    if (tid < 64) { sMv[tid] = -1e30f; sLv[tid] = 0.f; }

    float o[8][4];
#pragma unroll
    for (int j = 0; j < 8; j++)
#pragma unroll
        for (int k = 0; k < 4; k++) o[j][k] = 0.f;

    for (int ks = kbeg; ks < kend; ks += 128) {
        __syncthreads();
#pragma unroll
        for (int it = 0; it < 8; it++) {
            int idx = tid + 256 * it;
            int row = idx >> 4, c = idx & 15;
            CPA16(sb + (O_KHI + row * AST + c * 4) * 4,
                  (const char*)g_Khi + ((size_t)(tokb + ks + row) * DH + c * 8) * 2);
            CPA16(sb + (O_KLO + row * AST + c * 4) * 4,
                  (const char*)g_Klo + ((size_t)(tokb + ks + row) * DH + c * 8) * 2);
            CPA16(sb + (O_VHI + row * AST + c * 4) * 4,
                  (const char*)g_Vthi + ((size_t)row * NTOK + tokb + ks + c * 8) * 2);
            CPA16(sb + (O_VLO + row * AST + c * 4) * 4,
                  (const char*)g_Vtlo + ((size_t)row * NTOK + tokb + ks + c * 8) * 2);
        }
        CPA_COMMIT();
        CPA_WAIT0();
        __syncthreads();

        // ---- S = Q K^T ----
        float s_[8][4];
#pragma unroll
        for (int j = 0; j < 8; j++)
#pragma unroll
            for (int k = 0; k < 4; k++) s_[j][k] = 0.f;
#pragma unroll
        for (int k8 = 0; k8 < 8; k8++) {
            const int base = k8 * 8 + lk;
            const uint32_t* qh = smu + O_QHI + (m_base + lq4) * AST;
            const uint32_t* ql = smu + O_QLO + (m_base + lq4) * AST;
            uint32_t ah[4] = {qh[base], qh[base + 8 * AST], qh[base + 4], qh[base + 8 * AST + 4]};
            uint32_t al[4] = {ql[base], ql[base + 8 * AST], ql[base + 4], ql[base + 8 * AST + 4]};
#pragma unroll
            for (int nt = 0; nt < 8; nt++) {
                const uint32_t* kh = smu + O_KHI + (n_base + nt * 8 + lq4) * AST;
                const uint32_t* kl = smu + O_KLO + (n_base + nt * 8 + lq4) * AST;
                uint32_t bh[2] = {kh[base], kh[base + 4]};
                uint32_t bl[2] = {kl[base], kl[base + 4]};
                mma16(s_[nt], ah, bh);
                mma16(s_[nt], ah, bl);
                mma16(s_[nt], al, bh);
            }
        }

        // ---- causal mask ----
        if (ks + 128 > q0) {
            const int q_lo = q0 + m_base + lq4, q_hi = q_lo + 8;
#pragma unroll
            for (int nt = 0; nt < 8; nt++) {
                const int key0 = ks + n_base + nt * 8 + 2 * lk;
                if (key0 > q_lo)     s_[nt][0] = -1e30f;
                if (key0 + 1 > q_lo) s_[nt][1] = -1e30f;
                if (key0 > q_hi)     s_[nt][2] = -1e30f;
                if (key0 + 1 > q_hi) s_[nt][3] = -1e30f;
            }
        }

        // ---- online softmax (log2 units) ----
        const int r_lo = m_base + lq4, r_hi = r_lo + 8;
        float mx0 = -1e30f, mx1 = -1e30f;
#pragma unroll
        for (int nt = 0; nt < 8; nt++) {
            mx0 = fmaxf(mx0, fmaxf(s_[nt][0], s_[nt][1]));
            mx1 = fmaxf(mx1, fmaxf(s_[nt][2], s_[nt][3]));
        }
        mx0 = fmaxf(mx0, __shfl_xor_sync(0xffffffffu, mx0, 1));
        mx0 = fmaxf(mx0, __shfl_xor_sync(0xffffffffu, mx0, 2));
        mx1 = fmaxf(mx1, __shfl_xor_sync(0xffffffffu, mx1, 1));
        mx1 = fmaxf(mx1, __shfl_xor_sync(0xffffffffu, mx1, 2));
        if (lk == 0) {
            sRm[warp_n * 64 + r_lo] = mx0;
            sRm[warp_n * 64 + r_hi] = mx1;
        }
        __syncthreads();

        float m_lo = sMv[r_lo], m_hi = sMv[r_hi];
        float mn_lo = fmaxf(m_lo, fmaxf(sRm[r_lo], sRm[64 + r_lo]));
        float mn_hi = fmaxf(m_hi, fmaxf(sRm[r_hi], sRm[64 + r_hi]));
        float al_lo = ex2f(m_lo - mn_lo);
        float al_hi = ex2f(m_hi - mn_hi);

        float ps_lo = 0.f, ps_hi = 0.f;
#pragma unroll
        for (int nt = 0; nt < 8; nt++) {
            const int pi = warp_n * 32 + nt * 4 + lk;
            float p0 = ex2f(s_[nt][0] - mn_lo);
            float p1 = ex2f(s_[nt][1] - mn_lo);
            float p2 = ex2f(s_[nt][2] - mn_hi);
            float p3 = ex2f(s_[nt][3] - mn_hi);
            ps_lo += p0 + p1;
            ps_hi += p2 + p3;
            uint32_t hp, lp;
            split2(p0, p1, hp, lp);
            smu[O_PHI + r_lo * AST + pi] = hp;
            smu[O_PLO + r_lo * AST + pi] = lp;
            split2(p2, p3, hp, lp);
            smu[O_PHI + r_hi * AST + pi] = hp;
            smu[O_PLO + r_hi * AST + pi] = lp;
            o[nt][0] *= al_lo; o[nt][1] *= al_lo;
            o[nt][2] *= al_hi; o[nt][3] *= al_hi;
        }
        ps_lo += __shfl_xor_sync(0xffffffffu, ps_lo, 1);
        ps_lo += __shfl_xor_sync(0xffffffffu, ps_lo, 2);
        ps_hi += __shfl_xor_sync(0xffffffffu, ps_hi, 1);
        ps_hi += __shfl_xor_sync(0xffffffffu, ps_hi, 2);
        if (lk == 0) {
            sRl[warp_n * 64 + r_lo] = ps_lo;
            sRl[warp_n * 64 + r_hi] = ps_hi;
        }
        __syncthreads();

        if (warp_n == 0 && lk == 0) {
            sLv[r_lo] = sLv[r_lo] * al_lo + sRl[r_lo] + sRl[64 + r_lo];
            sLv[r_hi] = sLv[r_hi] * al_hi + sRl[r_hi] + sRl[64 + r_hi];
            sMv[r_lo] = mn_lo;
            sMv[r_hi] = mn_hi;
        }

        // ---- O += P V ----
#pragma unroll
        for (int k8 = 0; k8 < 8; k8++) {
            const int base = k8 * 8 + lk;
            const uint32_t* ph = smu + O_PHI + (m_base + lq4) * AST;
            const uint32_t* pl = smu + O_PLO + (m_base + lq4) * AST;
            uint32_t ah[4] = {ph[base], ph[base + 8 * AST], ph[base + 4], ph[base + 8 * AST + 4]};
            uint32_t al[4] = {pl[base], pl[base + 8 * AST], pl[base + 4], pl[base + 8 * AST + 4]};
#pragma unroll
            for (int nt = 0; nt < 8; nt++) {
                const uint32_t* vh = smu + O_VHI + (n_base + nt * 8 + lq4) * AST;
                const uint32_t* vl = smu + O_VLO + (n_base + nt * 8 + lq4) * AST;
                uint32_t bh[2] = {vh[base], vh[base + 4]};
                uint32_t bl[2] = {vl[base], vl[base + 4]};
                mma16(o[nt], ah, bh);
                mma16(o[nt], ah, bl);
                mma16(o[nt], al, bh);
            }
        }
    }

    __syncthreads();
    const int base = ((b * 32 + qt) * 4 + chunk) * 64;
#pragma unroll
    for (int h = 0; h < 2; h++) {
        const int row = m_base + lq4 + 8 * h;
#pragma unroll
        for (int nt = 0; nt < 8; nt++) {
            const int col = n_base + nt * 8 + 2 * lk;
            *(float2*)&g_Op[(size_t)(base + row) * DH + col] =
                make_float2(o[nt][2 * h], o[nt][2 * h + 1]);
        }
    }
    if (tid < 64) {
        g_m[base + tid] = sMv[tid];
        g_l[base + tid] = sLv[tid];
    }
}

// ---------------------------------------------------------------------------
__global__ __launch_bounds__(256) void attn_combine(float* __restrict__ out)
{
    const int qt = blockIdx.x, b = blockIdx.y;
    const int tid = threadIdx.x;
    const int q = tid >> 2, d0 = (tid & 3) * 32;
    const int nch = qt / 8 + 1;
    const int base = (b * 32 + qt) * 4 * 64 + q;

    float mm[4], ww[4];
    float M = -1e30f;
    for (int c = 0; c < nch; c++) { mm[c] = g_m[base + c * 64]; M = fmaxf(M, mm[c]); }
    float L = 0.f;
    for (int c = 0; c < nch; c++) { ww[c] = ex2f(mm[c] - M); L += g_l[base + c * 64] * ww[c]; }
    float inv = 1.f / L;

    float* op = out + (size_t)(b * TSEQ + qt * 64 + q) * DH + d0;
#pragma unroll
    for (int d = 0; d < 32; d += 4) {
        float4 a = make_float4(0.f, 0.f, 0.f, 0.f);
        for (int c = 0; c < nch; c++) {
            const float4 v = *(const float4*)(g_Op + (size_t)(base + c * 64) * DH + d0 + d);
            a.x += ww[c] * v.x; a.y += ww[c] * v.y;
            a.z += ww[c] * v.z; a.w += ww[c] * v.w;
        }
        a.x *= inv; a.y *= inv; a.z *= inv; a.w *= inv;
        *(float4*)(op + d) = a;
    }
}

// ---------------------------------------------------------------------------
extern "C" void kernel_launch(void* const* d_in, const int* in_sizes, int n_in,
                              void* d_out, int out_size)
{
    const float* x     = (const float*)d_in[0];
    const float* Wq    = (const float*)d_in[1];
    const float* Wk    = (const float*)d_in[2];
    const float* Wv    = (const float*)d_in[3];
    const float* theta = (const float*)d_in[4];
    float* out = (float*)d_out;

    cudaFuncSetAttribute(attn_part, cudaFuncAttributeMaxDynamicSharedMemorySize, AT_SMEM);

    rope_table<<<TSEQ, 128>>>(theta);

    dim3 g1(NTOK / 128, 3);
    qkv_mma<<<g1, 256>>>(x, Wq, Wk, Wv);

    attn_part<<<320, 256, AT_SMEM>>>(0);

    dim3 g3(32, 4);
    attn_combine<<<g3, 256>>>(out);
}

// round 8
// speedup vs baseline: 25.1179x; 1.0374x over previous
#include <cuda_runtime.h>
#include <cuda_bf16.h>
#include <math.h>
#include <stdint.h>

#define TSEQ   2048
#define NTOK   8192
#define DM     1024
#define DH     128
#define QSCALE 0.03125f                 // 1/sqrt(1024)
#define LOG2E  1.4426950408889634f

// Q,K token-major bf16 hi/lo planes; Vt transposed [DH][NTOK] planes.
__device__ unsigned short g_Qhi[NTOK * DH], g_Qlo[NTOK * DH];
__device__ unsigned short g_Khi[NTOK * DH], g_Klo[NTOK * DH];
__device__ unsigned short g_Vthi[DH * NTOK], g_Vtlo[DH * NTOK];
__device__ float g_ctab[TSEQ * DH];
__device__ float g_stab[TSEQ * DH];
// split-K partials: [b][qt][chunk][64 q][128 d]; m/l in log2 units
__device__ float g_Op[4 * 32 * 4 * 64 * DH];
__device__ float g_m [4 * 32 * 4 * 64];
__device__ float g_l [4 * 32 * 4 * 64];

__device__ __forceinline__ float ex2f(float x) {
    float y; asm("ex2.approx.ftz.f32 %0, %1;" : "=f"(y) : "f"(x)); return y;
}
__device__ __forceinline__ uint32_t s2u(const void* p) {
    uint32_t a;
    asm("{ .reg .u64 t; cvta.to.shared.u64 t, %1; cvt.u32.u64 %0, t; }"
        : "=r"(a) : "l"(p));
    return a;
}
#define CPA16(dst, src) \
    asm volatile("cp.async.cg.shared.global [%0], [%1], 16;" :: "r"(dst), "l"(src) : "memory")
#define CPA_COMMIT() asm volatile("cp.async.commit_group;" ::: "memory")
#define CPA_WAIT0()  asm volatile("cp.async.wait_group 0;" ::: "memory")
#define CPA_WAIT1()  asm volatile("cp.async.wait_group 1;" ::: "memory")

// bf16 m16n8k16 HMMA (sm_80 baseline PTX; runs on .target sm_103)
__device__ __forceinline__ void mma16(float* c, const uint32_t* a, const uint32_t* b) {
    asm volatile(
        "mma.sync.aligned.m16n8k16.row.col.f32.bf16.bf16.f32 "
        "{%0,%1,%2,%3}, {%4,%5,%6,%7}, {%8,%9}, {%0,%1,%2,%3};"
        : "+f"(c[0]), "+f"(c[1]), "+f"(c[2]), "+f"(c[3])
        : "r"(a[0]), "r"(a[1]), "r"(a[2]), "r"(a[3]), "r"(b[0]), "r"(b[1]));
}

// split (f0,f1) into packed bf16x2 hi and lo pairs (element k in low half)
__device__ __forceinline__ void split2(float f0, float f1, uint32_t& hi, uint32_t& lo) {
    __nv_bfloat16 h0 = __float2bfloat16(f0);
    __nv_bfloat16 h1 = __float2bfloat16(f1);
    __nv_bfloat16 l0 = __float2bfloat16(f0 - __bfloat162float(h0));
    __nv_bfloat16 l1 = __float2bfloat16(f1 - __bfloat162float(h1));
    hi = (uint32_t)__bfloat16_as_ushort(h0) | ((uint32_t)__bfloat16_as_ushort(h1) << 16);
    lo = (uint32_t)__bfloat16_as_ushort(l0) | ((uint32_t)__bfloat16_as_ushort(l1) << 16);
}

// ---------------------------------------------------------------------------
__global__ __launch_bounds__(128) void rope_table(const float* __restrict__ theta) {
    int p = blockIdx.x, n = threadIdx.x;
    float s, c;
    sincosf((float)(p + 1) * theta[n], &s, &c);
    g_ctab[p * DH + n] = c;
    g_stab[p * DH + n] = s;
}

// ---------------------------------------------------------------------------
// QKV projection, bf16x3 mma (EXACT copy of the R6 passing version).
// grid (64 token-tiles, 3 mats), 256 thr (8 warps = 4m x 2n).
// ---------------------------------------------------------------------------
#define QS 20

__global__ __launch_bounds__(256, 2)
void qkv_mma(const float* __restrict__ x,  const float* __restrict__ Wq,
             const float* __restrict__ Wk, const float* __restrict__ Wv) {
    __shared__ uint32_t sXhi[128 * QS], sXlo[128 * QS];
    __shared__ uint32_t sWhi[128 * QS], sWlo[128 * QS];

    const int tid = threadIdx.x;
    const int lane = tid & 31, wid = tid >> 5;
    const int warp_m = wid & 3, warp_n = wid >> 2;
    const int m_base = warp_m * 32, n_base = warp_n * 64;
    const int lq4 = lane >> 2, lk = lane & 3;
    const int t0 = blockIdx.x * 128;
    const int mat = blockIdx.y;
    const float* __restrict__ W = (mat == 0) ? Wq : ((mat == 1) ? Wk : Wv);

    const int lrow = tid >> 1, lseg = tid & 1;
    const float* gx = x + (size_t)(t0 + lrow) * DM + lseg * 16;
    const float* gw = W + (size_t)lrow * DM + lseg * 16;

    float4 rx[4], rw[4];
#pragma unroll
    for (int c = 0; c < 4; c++) {
        rx[c] = *(const float4*)(gx + c * 4);
        rw[c] = *(const float4*)(gw + c * 4);
    }

    float acc[2][8][4];
#pragma unroll
    for (int i = 0; i < 2; i++)
#pragma unroll
        for (int j = 0; j < 8; j++)
#pragma unroll
            for (int k = 0; k < 4; k++) acc[i][j][k] = 0.f;

    for (int ci = 0; ci < 32; ci++) {
        __syncthreads();
        {
            uint32_t hp[8], lp[8];
            const int sb = lrow * QS + lseg * 8;
#pragma unroll
            for (int c = 0; c < 4; c++) {
                split2(rx[c].x, rx[c].y, hp[2 * c],     lp[2 * c]);
                split2(rx[c].z, rx[c].w, hp[2 * c + 1], lp[2 * c + 1]);
            }
            *(uint4*)&sXhi[sb]     = make_uint4(hp[0], hp[1], hp[2], hp[3]);
            *(uint4*)&sXhi[sb + 4] = make_uint4(hp[4], hp[5], hp[6], hp[7]);
            *(uint4*)&sXlo[sb]     = make_uint4(lp[0], lp[1], lp[2], lp[3]);
            *(uint4*)&sXlo[sb + 4] = make_uint4(lp[4], lp[5], lp[6], lp[7]);
#pragma unroll
            for (int c = 0; c < 4; c++) {
                split2(rw[c].x, rw[c].y, hp[2 * c],     lp[2 * c]);
                split2(rw[c].z, rw[c].w, hp[2 * c + 1], lp[2 * c + 1]);
            }
            *(uint4*)&sWhi[sb]     = make_uint4(hp[0], hp[1], hp[2], hp[3]);
            *(uint4*)&sWhi[sb + 4] = make_uint4(hp[4], hp[5], hp[6], hp[7]);
            *(uint4*)&sWlo[sb]     = make_uint4(lp[0], lp[1], lp[2], lp[3]);
            *(uint4*)&sWlo[sb + 4] = make_uint4(lp[4], lp[5], lp[6], lp[7]);
        }
        __syncthreads();
        if (ci < 31) {
            const float* gx2 = gx + (ci + 1) * 32;
            const float* gw2 = gw + (ci + 1) * 32;
#pragma unroll
            for (int c = 0; c < 4; c++) {
                rx[c] = *(const float4*)(gx2 + c * 4);
                rw[c] = *(const float4*)(gw2 + c * 4);
            }
        }
#pragma unroll
        for (int kk = 0; kk < 2; kk++) {
            const int base = kk * 8 + lk;
            uint32_t ah[2][4], al[2][4];
#pragma unroll
            for (int mt = 0; mt < 2; mt++) {
                const uint32_t* ph = &sXhi[(m_base + mt * 16 + lq4) * QS];
                const uint32_t* pl = &sXlo[(m_base + mt * 16 + lq4) * QS];
                ah[mt][0] = ph[base];          ah[mt][1] = ph[base + 8 * QS];
                ah[mt][2] = ph[base + 4];      ah[mt][3] = ph[base + 8 * QS + 4];
                al[mt][0] = pl[base];          al[mt][1] = pl[base + 8 * QS];
                al[mt][2] = pl[base + 4];      al[mt][3] = pl[base + 8 * QS + 4];
            }
#pragma unroll
            for (int nt = 0; nt < 8; nt++) {
                const uint32_t* ph = &sWhi[(n_base + nt * 8 + lq4) * QS];
                const uint32_t* pl = &sWlo[(n_base + nt * 8 + lq4) * QS];
                uint32_t bh[2] = {ph[base], ph[base + 4]};
                uint32_t bl[2] = {pl[base], pl[base + 4]};
#pragma unroll
                for (int mt = 0; mt < 2; mt++) {
                    mma16(acc[mt][nt], ah[mt], bh);
                    mma16(acc[mt][nt], ah[mt], bl);
                    mma16(acc[mt][nt], al[mt], bh);
                }
            }
        }
    }

    // ---- epilogue ----
    if (mat < 2) {
        const float sc = (mat == 0) ? (QSCALE * LOG2E) : 1.f;
        unsigned short* dhi = (mat == 0) ? g_Qhi : g_Khi;
        unsigned short* dlo = (mat == 0) ? g_Qlo : g_Klo;
#pragma unroll
        for (int mt = 0; mt < 2; mt++)
#pragma unroll
            for (int h = 0; h < 2; h++) {
                const int tok = t0 + m_base + mt * 16 + lq4 + 8 * h;
                const int pos = tok & (TSEQ - 1);
#pragma unroll
                for (int nt = 0; nt < 8; nt++) {
                    const int colE = n_base + nt * 8 + 2 * lk;
                    float e = acc[mt][nt][2 * h] * sc;
                    float o = acc[mt][nt][2 * h + 1] * sc;
                    float ct = g_ctab[pos * DH + colE];
                    float st = g_stab[pos * DH + colE];
                    float re = e * ct + o * st;
                    float ro = o * ct - e * st;
                    uint32_t hi, lo;
                    split2(re, ro, hi, lo);
                    *(uint32_t*)&dhi[(size_t)tok * DH + colE] = hi;
                    *(uint32_t*)&dlo[(size_t)tok * DH + colE] = lo;
                }
            }
    } else {
#pragma unroll
        for (int mt = 0; mt < 2; mt++)
#pragma unroll
            for (int h = 0; h < 2; h++) {
                const int tok = t0 + m_base + mt * 16 + lq4 + 8 * h;
#pragma unroll
                for (int nt = 0; nt < 8; nt++) {
                    const int colE = n_base + nt * 8 + 2 * lk;
#pragma unroll
                    for (int e = 0; e < 2; e++) {
                        float v = acc[mt][nt][2 * h + e];
                        __nv_bfloat16 hb = __float2bfloat16(v);
                        __nv_bfloat16 lb = __float2bfloat16(v - __bfloat162float(hb));
                        g_Vthi[(size_t)(colE + e) * NTOK + tok] = __bfloat16_as_ushort(hb);
                        g_Vtlo[(size_t)(colE + e) * NTOK + tok] = __bfloat16_as_ushort(lb);
                    }
                }
            }
    }
}

// ---------------------------------------------------------------------------
// Flash attention partials, bf16x3 mma, software-pipelined K/V loads.
// 320 blocks x 256 threads (8 warps: 4m x 2n).
// Commit-group order: [Q+K0], [V0], then per tile [K_next], [V_next].
// ---------------------------------------------------------------------------
#define AST 68
#define O_QHI 0
#define O_QLO (O_QHI + 64 * AST)
#define O_KHI (O_QLO + 64 * AST)
#define O_KLO (O_KHI + 128 * AST)
#define O_VHI (O_KLO + 128 * AST)
#define O_VLO (O_VHI + 128 * AST)
#define O_PHI (O_VLO + 128 * AST)
#define O_PLO (O_PHI + 64 * AST)
#define O_F   (O_PLO + 64 * AST)
#define AT_SMEM ((O_F + 384) * 4)

__global__ __launch_bounds__(256, 1) void attn_part(int dummy)
{
    extern __shared__ uint32_t smu[];
    float* sMv = (float*)(smu + O_F);
    float* sLv = sMv + 64;
    float* sRm = sLv + 64;      // [2][64]
    float* sRl = sRm + 128;     // [2][64]
    const uint32_t sb = s2u(smu);

    const int tid = threadIdx.x;
    const int lane = tid & 31, wid = tid >> 5;
    const int warp_m = wid & 3, warp_n = wid >> 2;
    const int m_base = warp_m * 16, n_base = warp_n * 64;
    const int lq4 = lane >> 2, lk = lane & 3;

    // block -> (b, qt, chunk)
    int r = blockIdx.x % 80;
    int b = blockIdx.x / 80;
    int qt, chunk;
    if (r < 8)       { qt = r;                 chunk = 0; }
    else if (r < 24) { qt = 8  + (r - 8) / 2;  chunk = (r - 8) % 2; }
    else if (r < 48) { qt = 16 + (r - 24) / 3; chunk = (r - 24) % 3; }
    else             { qt = 24 + (r - 48) / 4; chunk = (r - 48) % 4; }

    const int q0   = qt * 64;
    const int kbeg = chunk * 512;
    const int kend = min(q0 + 64, kbeg + 512);
    const int tokb = b * TSEQ;

    auto loadK = [&](int ks_) {
#pragma unroll
        for (int it = 0; it < 8; it++) {
            int idx = tid + 256 * it;
            int row = idx >> 4, c = idx & 15;
            CPA16(sb + (O_KHI + row * AST + c * 4) * 4,
                  (const char*)g_Khi + ((size_t)(tokb + ks_ + row) * DH + c * 8) * 2);
            CPA16(sb + (O_KLO + row * AST + c * 4) * 4,
                  (const char*)g_Klo + ((size_t)(tokb + ks_ + row) * DH + c * 8) * 2);
        }
    };
    auto loadV = [&](int ks_) {
#pragma unroll
        for (int it = 0; it < 8; it++) {
            int idx = tid + 256 * it;
            int row = idx >> 4, c = idx & 15;
            CPA16(sb + (O_VHI + row * AST + c * 4) * 4,
                  (const char*)g_Vthi + ((size_t)row * NTOK + tokb + ks_ + c * 8) * 2);
            CPA16(sb + (O_VLO + row * AST + c * 4) * 4,
                  (const char*)g_Vtlo + ((size_t)row * NTOK + tokb + ks_ + c * 8) * 2);
        }
    };

    // group0: Q + K0    group1: V0
#pragma unroll
    for (int it = 0; it < 4; it++) {
        int idx = tid + 256 * it;
        int row = idx >> 4, c = idx & 15;
        CPA16(sb + (O_QHI + row * AST + c * 4) * 4,
              (const char*)g_Qhi + ((size_t)(tokb + q0 + row) * DH + c * 8) * 2);
        CPA16(sb + (O_QLO + row * AST + c * 4) * 4,
              (const char*)g_Qlo + ((size_t)(tokb + q0 + row) * DH + c * 8) * 2);
    }
    loadK(kbeg);
    CPA_COMMIT();
    loadV(kbeg);
    CPA_COMMIT();

    if (tid < 64) { sMv[tid] = -1e30f; sLv[tid] = 0.f; }

    float o[8][4];
#pragma unroll
    for (int j = 0; j < 8; j++)
#pragma unroll
        for (int k = 0; k < 4; k++) o[j][k] = 0.f;

    for (int ks = kbeg; ks < kend; ks += 128) {
        const bool last = (ks + 128 >= kend);
        CPA_WAIT1();               // Q+K_cur resident; V_cur may be in flight
        __syncthreads();

        // ---- S = Q K^T ----
        float s_[8][4];
#pragma unroll
        for (int j = 0; j < 8; j++)
#pragma unroll
            for (int k = 0; k < 4; k++) s_[j][k] = 0.f;
#pragma unroll
        for (int k8 = 0; k8 < 8; k8++) {
            const int base = k8 * 8 + lk;
            const uint32_t* qh = smu + O_QHI + (m_base + lq4) * AST;
            const uint32_t* ql = smu + O_QLO + (m_base + lq4) * AST;
            uint32_t ah[4] = {qh[base], qh[base + 8 * AST], qh[base + 4], qh[base + 8 * AST + 4]};
            uint32_t al[4] = {ql[base], ql[base + 8 * AST], ql[base + 4], ql[base + 8 * AST + 4]};
#pragma unroll
            for (int nt = 0; nt < 8; nt++) {
                const uint32_t* kh = smu + O_KHI + (n_base + nt * 8 + lq4) * AST;
                const uint32_t* kl = smu + O_KLO + (n_base + nt * 8 + lq4) * AST;
                uint32_t bh[2] = {kh[base], kh[base + 4]};
                uint32_t bl[2] = {kl[base], kl[base + 4]};
                mma16(s_[nt], ah, bh);
                mma16(s_[nt], ah, bl);
                mma16(s_[nt], al, bh);
            }
        }

        // ---- causal mask ----
        if (ks + 128 > q0) {
            const int q_lo = q0 + m_base + lq4, q_hi = q_lo + 8;
#pragma unroll
            for (int nt = 0; nt < 8; nt++) {
                const int key0 = ks + n_base + nt * 8 + 2 * lk;
                if (key0 > q_lo)     s_[nt][0] = -1e30f;
                if (key0 + 1 > q_lo) s_[nt][1] = -1e30f;
                if (key0 > q_hi)     s_[nt][2] = -1e30f;
                if (key0 + 1 > q_hi) s_[nt][3] = -1e30f;
            }
        }

        // ---- online softmax (log2 units) ----
        const int r_lo = m_base + lq4, r_hi = r_lo + 8;
        float mx0 = -1e30f, mx1 = -1e30f;
#pragma unroll
        for (int nt = 0; nt < 8; nt++) {
            mx0 = fmaxf(mx0, fmaxf(s_[nt][0], s_[nt][1]));
            mx1 = fmaxf(mx1, fmaxf(s_[nt][2], s_[nt][3]));
        }
        mx0 = fmaxf(mx0, __shfl_xor_sync(0xffffffffu, mx0, 1));
        mx0 = fmaxf(mx0, __shfl_xor_sync(0xffffffffu, mx0, 2));
        mx1 = fmaxf(mx1, __shfl_xor_sync(0xffffffffu, mx1, 1));
        mx1 = fmaxf(mx1, __shfl_xor_sync(0xffffffffu, mx1, 2));
        if (lk == 0) {
            sRm[warp_n * 64 + r_lo] = mx0;
            sRm[warp_n * 64 + r_hi] = mx1;
        }
        __syncthreads();           // all warps past S reads -> K buffer free

        if (!last) { loadK(ks + 128); CPA_COMMIT(); }

        float m_lo = sMv[r_lo], m_hi = sMv[r_hi];
        float mn_lo = fmaxf(m_lo, fmaxf(sRm[r_lo], sRm[64 + r_lo]));
        float mn_hi = fmaxf(m_hi, fmaxf(sRm[r_hi], sRm[64 + r_hi]));
        float al_lo = ex2f(m_lo - mn_lo);
        float al_hi = ex2f(m_hi - mn_hi);

        float ps_lo = 0.f, ps_hi = 0.f;
#pragma unroll
        for (int nt = 0; nt < 8; nt++) {
            const int pi = warp_n * 32 + nt * 4 + lk;
            float p0 = ex2f(s_[nt][0] - mn_lo);
            float p1 = ex2f(s_[nt][1] - mn_lo);
            float p2 = ex2f(s_[nt][2] - mn_hi);
            float p3 = ex2f(s_[nt][3] - mn_hi);
            ps_lo += p0 + p1;
            ps_hi += p2 + p3;
            uint32_t hp, lp;
            split2(p0, p1, hp, lp);
            smu[O_PHI + r_lo * AST + pi] = hp;
            smu[O_PLO + r_lo * AST + pi] = lp;
            split2(p2, p3, hp, lp);
            smu[O_PHI + r_hi * AST + pi] = hp;
            smu[O_PLO + r_hi * AST + pi] = lp;
            o[nt][0] *= al_lo; o[nt][1] *= al_lo;
            o[nt][2] *= al_hi; o[nt][3] *= al_hi;
        }
        ps_lo += __shfl_xor_sync(0xffffffffu, ps_lo, 1);
        ps_lo += __shfl_xor_sync(0xffffffffu, ps_lo, 2);
        ps_hi += __shfl_xor_sync(0xffffffffu, ps_hi, 1);
        ps_hi += __shfl_xor_sync(0xffffffffu, ps_hi, 2);
        if (lk == 0) {
            sRl[warp_n * 64 + r_lo] = ps_lo;
            sRl[warp_n * 64 + r_hi] = ps_hi;
        }

        if (last) { CPA_WAIT0(); } else { CPA_WAIT1(); }   // V_cur resident
        __syncthreads();

        if (warp_n == 0 && lk == 0) {
            sLv[r_lo] = sLv[r_lo] * al_lo + sRl[r_lo] + sRl[64 + r_lo];
            sLv[r_hi] = sLv[r_hi] * al_hi + sRl[r_hi] + sRl[64 + r_hi];
            sMv[r_lo] = mn_lo;
            sMv[r_hi] = mn_hi;
        }

        // ---- O += P V ----
#pragma unroll
        for (int k8 = 0; k8 < 8; k8++) {
            const int base = k8 * 8 + lk;
            const uint32_t* ph = smu + O_PHI + (m_base + lq4) * AST;
            const uint32_t* pl = smu + O_PLO + (m_base + lq4) * AST;
            uint32_t ah[4] = {ph[base], ph[base + 8 * AST], ph[base + 4], ph[base + 8 * AST + 4]};
            uint32_t al[4] = {pl[base], pl[base + 8 * AST], pl[base + 4], pl[base + 8 * AST + 4]};
#pragma unroll
            for (int nt = 0; nt < 8; nt++) {
                const uint32_t* vh = smu + O_VHI + (n_base + nt * 8 + lq4) * AST;
                const uint32_t* vl = smu + O_VLO + (n_base + nt * 8 + lq4) * AST;
                uint32_t bh[2] = {vh[base], vh[base + 4]};
                uint32_t bl[2] = {vl[base], vl[base + 4]};
                mma16(o[nt], ah, bh);
                mma16(o[nt], ah, bl);
                mma16(o[nt], al, bh);
            }
        }

        if (!last) {
            __syncthreads();       // PV done in all warps -> V buffer free
            loadV(ks + 128);
            CPA_COMMIT();
        }
    }

    __syncthreads();
    const int base = ((b * 32 + qt) * 4 + chunk) * 64;
#pragma unroll
    for (int h = 0; h < 2; h++) {
        const int row = m_base + lq4 + 8 * h;
#pragma unroll
        for (int nt = 0; nt < 8; nt++) {
            const int col = n_base + nt * 8 + 2 * lk;
            *(float2*)&g_Op[(size_t)(base + row) * DH + col] =
                make_float2(o[nt][2 * h], o[nt][2 * h + 1]);
        }
    }
    if (tid < 64) {
        g_m[base + tid] = sMv[tid];
        g_l[base + tid] = sLv[tid];
    }
}

// ---------------------------------------------------------------------------
// Combine: grid (32 qt, 4 b, 2 q-halves), 256 thr; thread = 16 d of one q row.
// ---------------------------------------------------------------------------
__global__ __launch_bounds__(256) void attn_combine(float* __restrict__ out)
{
    const int qt = blockIdx.x, b = blockIdx.y;
    const int tid = threadIdx.x;
    const int q = blockIdx.z * 32 + (tid >> 3);
    const int d0 = (tid & 7) * 16;
    const int nch = qt / 8 + 1;
    const int base = (b * 32 + qt) * 256 + q;   // chunk stride = 64

    float mm[4];
    int cc[4];
#pragma unroll
    for (int c = 0; c < 4; c++) {
        cc[c] = (c < nch) ? c : (nch - 1);
        mm[c] = g_m[base + cc[c] * 64];
    }
    float M = fmaxf(fmaxf(mm[0], mm[1]), fmaxf(mm[2], mm[3]));
    float ww[4], L = 0.f;
#pragma unroll
    for (int c = 0; c < 4; c++) {
        ww[c] = (c < nch) ? ex2f(mm[c] - M) : 0.f;
        L += ww[c] * g_l[base + cc[c] * 64];
    }
    const float inv = 1.f / L;

    float* op = out + (size_t)(b * TSEQ + qt * 64 + q) * DH + d0;
#pragma unroll
    for (int d = 0; d < 16; d += 4) {
        float4 a = make_float4(0.f, 0.f, 0.f, 0.f);
#pragma unroll
        for (int c = 0; c < 4; c++) {
            const float4 v = *(const float4*)(g_Op + (size_t)(base + cc[c] * 64) * DH + d0 + d);
            a.x += ww[c] * v.x; a.y += ww[c] * v.y;
            a.z += ww[c] * v.z; a.w += ww[c] * v.w;
        }
        a.x *= inv; a.y *= inv; a.z *= inv; a.w *= inv;
        *(float4*)(op + d) = a;
    }
}

// ---------------------------------------------------------------------------
extern "C" void kernel_launch(void* const* d_in, const int* in_sizes, int n_in,
                              void* d_out, int out_size)
{
    const float* x     = (const float*)d_in[0];
    const float* Wq    = (const float*)d_in[1];
    const float* Wk    = (const float*)d_in[2];
    const float* Wv    = (const float*)d_in[3];
    const float* theta = (const float*)d_in[4];
    float* out = (float*)d_out;

    cudaFuncSetAttribute(attn_part, cudaFuncAttributeMaxDynamicSharedMemorySize, AT_SMEM);

    rope_table<<<TSEQ, 128>>>(theta);

    dim3 g1(NTOK / 128, 3);
    qkv_mma<<<g1, 256>>>(x, Wq, Wk, Wv);

    attn_part<<<320, 256, AT_SMEM>>>(0);

    dim3 g3(32, 4, 2);
    attn_combine<<<g3, 256>>>(out);
}

// round 9
// speedup vs baseline: 26.5277x; 1.0561x over previous
#include <cuda_runtime.h>
#include <cuda_bf16.h>
#include <math.h>
#include <stdint.h>

#define TSEQ   2048
#define NTOK   8192
#define DM     1024
#define DH     128
#define QSCALE 0.03125f                 // 1/sqrt(1024)
#define LOG2E  1.4426950408889634f

// bf16 hi/lo planes of inputs (pre-converted once per launch)
__device__ unsigned short g_Xhi[NTOK * DM], g_Xlo[NTOK * DM];
__device__ unsigned short g_Whi[3 * DH * DM], g_Wlo[3 * DH * DM];
// Q,K token-major bf16 hi/lo planes; Vt transposed [DH][NTOK] planes.
__device__ unsigned short g_Qhi[NTOK * DH], g_Qlo[NTOK * DH];
__device__ unsigned short g_Khi[NTOK * DH], g_Klo[NTOK * DH];
__device__ unsigned short g_Vthi[DH * NTOK], g_Vtlo[DH * NTOK];
__device__ float g_ctab[TSEQ * DH];
__device__ float g_stab[TSEQ * DH];
// split-K partials: [b][qt][chunk][64 q][128 d]; m/l in log2 units
__device__ float g_Op[4 * 32 * 4 * 64 * DH];
__device__ float g_m [4 * 32 * 4 * 64];
__device__ float g_l [4 * 32 * 4 * 64];

__device__ __forceinline__ float ex2f(float x) {
    float y; asm("ex2.approx.ftz.f32 %0, %1;" : "=f"(y) : "f"(x)); return y;
}
__device__ __forceinline__ uint32_t s2u(const void* p) {
    uint32_t a;
    asm("{ .reg .u64 t; cvta.to.shared.u64 t, %1; cvt.u32.u64 %0, t; }"
        : "=r"(a) : "l"(p));
    return a;
}
#define CPA16(dst, src) \
    asm volatile("cp.async.cg.shared.global [%0], [%1], 16;" :: "r"(dst), "l"(src) : "memory")
#define CPA_COMMIT() asm volatile("cp.async.commit_group;" ::: "memory")
#define CPA_WAIT0()  asm volatile("cp.async.wait_group 0;" ::: "memory")
#define CPA_WAIT1()  asm volatile("cp.async.wait_group 1;" ::: "memory")

// bf16 m16n8k16 HMMA
__device__ __forceinline__ void mma16(float* c, const uint32_t* a, const uint32_t* b) {
    asm volatile(
        "mma.sync.aligned.m16n8k16.row.col.f32.bf16.bf16.f32 "
        "{%0,%1,%2,%3}, {%4,%5,%6,%7}, {%8,%9}, {%0,%1,%2,%3};"
        : "+f"(c[0]), "+f"(c[1]), "+f"(c[2]), "+f"(c[3])
        : "r"(a[0]), "r"(a[1]), "r"(a[2]), "r"(a[3]), "r"(b[0]), "r"(b[1]));
}

__device__ __forceinline__ void split2(float f0, float f1, uint32_t& hi, uint32_t& lo) {
    __nv_bfloat16 h0 = __float2bfloat16(f0);
    __nv_bfloat16 h1 = __float2bfloat16(f1);
    __nv_bfloat16 l0 = __float2bfloat16(f0 - __bfloat162float(h0));
    __nv_bfloat16 l1 = __float2bfloat16(f1 - __bfloat162float(h1));
    hi = (uint32_t)__bfloat16_as_ushort(h0) | ((uint32_t)__bfloat16_as_ushort(h1) << 16);
    lo = (uint32_t)__bfloat16_as_ushort(l0) | ((uint32_t)__bfloat16_as_ushort(l1) << 16);
}

// ---------------------------------------------------------------------------
__global__ __launch_bounds__(128) void rope_table(const float* __restrict__ theta) {
    int p = blockIdx.x, n = threadIdx.x;
    float s, c;
    sincosf((float)(p + 1) * theta[n], &s, &c);
    g_ctab[p * DH + n] = c;
    g_stab[p * DH + n] = s;
}

// ---------------------------------------------------------------------------
// Pre-convert x and Wq/Wk/Wv to bf16 hi/lo planes.  8 floats per thread.
// ---------------------------------------------------------------------------
#define NX8 (NTOK * DM / 8)            // 1048576
#define NW8 (DH * DM / 8)              // 16384
__global__ __launch_bounds__(256) void convert_inputs(
    const float* __restrict__ x,  const float* __restrict__ Wq,
    const float* __restrict__ Wk, const float* __restrict__ Wv)
{
    size_t gid = (size_t)blockIdx.x * 256 + threadIdx.x;
    const float* src;
    unsigned short *dhi, *dlo;
    size_t e0;
    if (gid < NX8) {
        src = x; dhi = g_Xhi; dlo = g_Xlo; e0 = gid * 8;
    } else {
        size_t r = gid - NX8;
        int mat = (int)(r / NW8);
        size_t rr = r - (size_t)mat * NW8;
        src = (mat == 0) ? Wq : ((mat == 1) ? Wk : Wv);
        dhi = g_Whi + (size_t)mat * DH * DM;
        dlo = g_Wlo + (size_t)mat * DH * DM;
        e0 = rr * 8;
    }
    float4 a = *(const float4*)(src + e0);
    float4 b = *(const float4*)(src + e0 + 4);
    uint32_t hp[4], lp[4];
    split2(a.x, a.y, hp[0], lp[0]);
    split2(a.z, a.w, hp[1], lp[1]);
    split2(b.x, b.y, hp[2], lp[2]);
    split2(b.z, b.w, hp[3], lp[3]);
    *(uint4*)(dhi + e0) = make_uint4(hp[0], hp[1], hp[2], hp[3]);
    *(uint4*)(dlo + e0) = make_uint4(lp[0], lp[1], lp[2], lp[3]);
}

// ---------------------------------------------------------------------------
// QKV projection, bf16x3 mma, 2-stage cp.async pipeline on pre-split planes.
// grid (64 token-tiles, 3 mats), 256 thr (8 warps = 4m x 2n).
// Stage layout: [Xhi | Xlo | Whi | Wlo], each 128 rows x QS u32 (16 data+pad).
// ---------------------------------------------------------------------------
#define QS 20
#define QSTG (4 * 128 * QS)            // u32 per stage
#define QO_XHI 0
#define QO_XLO (128 * QS)
#define QO_WHI (2 * 128 * QS)
#define QO_WLO (3 * 128 * QS)
#define QKV_SMEM (2 * QSTG * 4)        // 81920 bytes

__global__ __launch_bounds__(256, 2)
void qkv_mma(int dummy) {
    extern __shared__ uint32_t qsm[];
    const uint32_t sbq = s2u(qsm);

    const int tid = threadIdx.x;
    const int lane = tid & 31, wid = tid >> 5;
    const int warp_m = wid & 3, warp_n = wid >> 2;
    const int m_base = warp_m * 32, n_base = warp_n * 64;
    const int lq4 = lane >> 2, lk = lane & 3;
    const int t0 = blockIdx.x * 128;
    const int mat = blockIdx.y;

    const unsigned short* wHi = g_Whi + (size_t)mat * DH * DM;
    const unsigned short* wLo = g_Wlo + (size_t)mat * DH * DM;

    const int lrow = tid >> 1, lhalf = tid & 1;    // 128 rows x 2 halves (16 elems)

    // Each thread: 16 bf16 elems (32 B) per plane = 2x CPA16, dst/src both +16B.
    auto loadChunk = [&](int ci, int st) {
        const size_t xb = ((size_t)(t0 + lrow) * DM + ci * 32 + lhalf * 16) * 2;
        const size_t wb = ((size_t)lrow * DM + ci * 32 + lhalf * 16) * 2;
        const uint32_t d0 = sbq + (st * QSTG + lrow * QS + lhalf * 8) * 4;
        CPA16(d0 + QO_XHI * 4,      (const char*)g_Xhi + xb);
        CPA16(d0 + QO_XHI * 4 + 16, (const char*)g_Xhi + xb + 16);
        CPA16(d0 + QO_XLO * 4,      (const char*)g_Xlo + xb);
        CPA16(d0 + QO_XLO * 4 + 16, (const char*)g_Xlo + xb + 16);
        CPA16(d0 + QO_WHI * 4,      (const char*)wHi + wb);
        CPA16(d0 + QO_WHI * 4 + 16, (const char*)wHi + wb + 16);
        CPA16(d0 + QO_WLO * 4,      (const char*)wLo + wb);
        CPA16(d0 + QO_WLO * 4 + 16, (const char*)wLo + wb + 16);
    };

    float acc[2][8][4];
#pragma unroll
    for (int i = 0; i < 2; i++)
#pragma unroll
        for (int j = 0; j < 8; j++)
#pragma unroll
            for (int k = 0; k < 4; k++) acc[i][j][k] = 0.f;

    loadChunk(0, 0);
    CPA_COMMIT();

    for (int ci = 0; ci < 32; ci++) {
        if (ci + 1 < 32) {
            loadChunk(ci + 1, (ci + 1) & 1);
            CPA_COMMIT();
            CPA_WAIT1();
        } else {
            CPA_WAIT0();
        }
        __syncthreads();

        const uint32_t* st = qsm + (ci & 1) * QSTG;
#pragma unroll
        for (int kk = 0; kk < 2; kk++) {
            const int base = kk * 8 + lk;
            uint32_t ah[2][4], al[2][4];
#pragma unroll
            for (int mt = 0; mt < 2; mt++) {
                const uint32_t* ph = st + QO_XHI + (m_base + mt * 16 + lq4) * QS;
                const uint32_t* pl = st + QO_XLO + (m_base + mt * 16 + lq4) * QS;
                ah[mt][0] = ph[base];     ah[mt][1] = ph[base + 8 * QS];
                ah[mt][2] = ph[base + 4]; ah[mt][3] = ph[base + 8 * QS + 4];
                al[mt][0] = pl[base];     al[mt][1] = pl[base + 8 * QS];
                al[mt][2] = pl[base + 4]; al[mt][3] = pl[base + 8 * QS + 4];
            }
#pragma unroll
            for (int nt = 0; nt < 8; nt++) {
                const uint32_t* ph = st + QO_WHI + (n_base + nt * 8 + lq4) * QS;
                const uint32_t* pl = st + QO_WLO + (n_base + nt * 8 + lq4) * QS;
                uint32_t bh[2] = {ph[base], ph[base + 4]};
                uint32_t bl[2] = {pl[base], pl[base + 4]};
#pragma unroll
                for (int mt = 0; mt < 2; mt++) {
                    mma16(acc[mt][nt], ah[mt], bh);
                    mma16(acc[mt][nt], ah[mt], bl);
                    mma16(acc[mt][nt], al[mt], bh);
                }
            }
        }
        __syncthreads();
    }

    // ---- epilogue ----
    if (mat < 2) {
        const float sc = (mat == 0) ? (QSCALE * LOG2E) : 1.f;
        unsigned short* dhi = (mat == 0) ? g_Qhi : g_Khi;
        unsigned short* dlo = (mat == 0) ? g_Qlo : g_Klo;
#pragma unroll
        for (int mt = 0; mt < 2; mt++)
#pragma unroll
            for (int h = 0; h < 2; h++) {
                const int tok = t0 + m_base + mt * 16 + lq4 + 8 * h;
                const int pos = tok & (TSEQ - 1);
#pragma unroll
                for (int nt = 0; nt < 8; nt++) {
                    const int colE = n_base + nt * 8 + 2 * lk;
                    float e = acc[mt][nt][2 * h] * sc;
                    float o = acc[mt][nt][2 * h + 1] * sc;
                    float ct = g_ctab[pos * DH + colE];
                    float st = g_stab[pos * DH + colE];
                    float re = e * ct + o * st;
                    float ro = o * ct - e * st;
                    uint32_t hi, lo;
                    split2(re, ro, hi, lo);
                    *(uint32_t*)&dhi[(size_t)tok * DH + colE] = hi;
                    *(uint32_t*)&dlo[(size_t)tok * DH + colE] = lo;
                }
            }
    } else {
#pragma unroll
        for (int mt = 0; mt < 2; mt++)
#pragma unroll
            for (int h = 0; h < 2; h++) {
                const int tok = t0 + m_base + mt * 16 + lq4 + 8 * h;
#pragma unroll
                for (int nt = 0; nt < 8; nt++) {
                    const int colE = n_base + nt * 8 + 2 * lk;
#pragma unroll
                    for (int e = 0; e < 2; e++) {
                        float v = acc[mt][nt][2 * h + e];
                        __nv_bfloat16 hb = __float2bfloat16(v);
                        __nv_bfloat16 lb = __float2bfloat16(v - __bfloat162float(hb));
                        g_Vthi[(size_t)(colE + e) * NTOK + tok] = __bfloat16_as_ushort(hb);
                        g_Vtlo[(size_t)(colE + e) * NTOK + tok] = __bfloat16_as_ushort(lb);
                    }
                }
            }
    }
}

// ---------------------------------------------------------------------------
// Flash attention partials, bf16x3 mma, software-pipelined K/V loads.
// (unchanged from R8 passing version)
// ---------------------------------------------------------------------------
#define AST 68
#define O_QHI 0
#define O_QLO (O_QHI + 64 * AST)
#define O_KHI (O_QLO + 64 * AST)
#define O_KLO (O_KHI + 128 * AST)
#define O_VHI (O_KLO + 128 * AST)
#define O_VLO (O_VHI + 128 * AST)
#define O_PHI (O_VLO + 128 * AST)
#define O_PLO (O_PHI + 64 * AST)
#define O_F   (O_PLO + 64 * AST)
#define AT_SMEM ((O_F + 384) * 4)

__global__ __launch_bounds__(256, 1) void attn_part(int dummy)
{
    extern __shared__ uint32_t smu[];
    float* sMv = (float*)(smu + O_F);
    float* sLv = sMv + 64;
    float* sRm = sLv + 64;      // [2][64]
    float* sRl = sRm + 128;     // [2][64]
    const uint32_t sb = s2u(smu);

    const int tid = threadIdx.x;
    const int lane = tid & 31, wid = tid >> 5;
    const int warp_m = wid & 3, warp_n = wid >> 2;
    const int m_base = warp_m * 16, n_base = warp_n * 64;
    const int lq4 = lane >> 2, lk = lane & 3;

    int r = blockIdx.x % 80;
    int b = blockIdx.x / 80;
    int qt, chunk;
    if (r < 8)       { qt = r;                 chunk = 0; }
    else if (r < 24) { qt = 8  + (r - 8) / 2;  chunk = (r - 8) % 2; }
    else if (r < 48) { qt = 16 + (r - 24) / 3; chunk = (r - 24) % 3; }
    else             { qt = 24 + (r - 48) / 4; chunk = (r - 48) % 4; }

    const int q0   = qt * 64;
    const int kbeg = chunk * 512;
    const int kend = min(q0 + 64, kbeg + 512);
    const int tokb = b * TSEQ;

    auto loadK = [&](int ks_) {
#pragma unroll
        for (int it = 0; it < 8; it++) {
            int idx = tid + 256 * it;
            int row = idx >> 4, c = idx & 15;
            CPA16(sb + (O_KHI + row * AST + c * 4) * 4,
                  (const char*)g_Khi + ((size_t)(tokb + ks_ + row) * DH + c * 8) * 2);
            CPA16(sb + (O_KLO + row * AST + c * 4) * 4,
                  (const char*)g_Klo + ((size_t)(tokb + ks_ + row) * DH + c * 8) * 2);
        }
    };
    auto loadV = [&](int ks_) {
#pragma unroll
        for (int it = 0; it < 8; it++) {
            int idx = tid + 256 * it;
            int row = idx >> 4, c = idx & 15;
            CPA16(sb + (O_VHI + row * AST + c * 4) * 4,
                  (const char*)g_Vthi + ((size_t)row * NTOK + tokb + ks_ + c * 8) * 2);
            CPA16(sb + (O_VLO + row * AST + c * 4) * 4,
                  (const char*)g_Vtlo + ((size_t)row * NTOK + tokb + ks_ + c * 8) * 2);
        }
    };

    // group0: Q + K0    group1: V0
#pragma unroll
    for (int it = 0; it < 4; it++) {
        int idx = tid + 256 * it;
        int row = idx >> 4, c = idx & 15;
        CPA16(sb + (O_QHI + row * AST + c * 4) * 4,
              (const char*)g_Qhi + ((size_t)(tokb + q0 + row) * DH + c * 8) * 2);
        CPA16(sb + (O_QLO + row * AST + c * 4) * 4,
              (const char*)g_Qlo + ((size_t)(tokb + q0 + row) * DH + c * 8) * 2);
    }
    loadK(kbeg);
    CPA_COMMIT();
    loadV(kbeg);
    CPA_COMMIT();

    if (tid < 64) { sMv[tid] = -1e30f; sLv[tid] = 0.f; }

    float o[8][4];
#pragma unroll
    for (int j = 0; j < 8; j++)
#pragma unroll
        for (int k = 0; k < 4; k++) o[j][k] = 0.f;

    for (int ks = kbeg; ks < kend; ks += 128) {
        const bool last = (ks + 128 >= kend);
        CPA_WAIT1();
        __syncthreads();

        float s_[8][4];
#pragma unroll
        for (int j = 0; j < 8; j++)
#pragma unroll
            for (int k = 0; k < 4; k++) s_[j][k] = 0.f;
#pragma unroll
        for (int k8 = 0; k8 < 8; k8++) {
            const int base = k8 * 8 + lk;
            const uint32_t* qh = smu + O_QHI + (m_base + lq4) * AST;
            const uint32_t* ql = smu + O_QLO + (m_base + lq4) * AST;
            uint32_t ah[4] = {qh[base], qh[base + 8 * AST], qh[base + 4], qh[base + 8 * AST + 4]};
            uint32_t al[4] = {ql[base], ql[base + 8 * AST], ql[base + 4], ql[base + 8 * AST + 4]};
#pragma unroll
            for (int nt = 0; nt < 8; nt++) {
                const uint32_t* kh = smu + O_KHI + (n_base + nt * 8 + lq4) * AST;
                const uint32_t* kl = smu + O_KLO + (n_base + nt * 8 + lq4) * AST;
                uint32_t bh[2] = {kh[base], kh[base + 4]};
                uint32_t bl[2] = {kl[base], kl[base + 4]};
                mma16(s_[nt], ah, bh);
                mma16(s_[nt], ah, bl);
                mma16(s_[nt], al, bh);
            }
        }

        if (ks + 128 > q0) {
            const int q_lo = q0 + m_base + lq4, q_hi = q_lo + 8;
#pragma unroll
            for (int nt = 0; nt < 8; nt++) {
                const int key0 = ks + n_base + nt * 8 + 2 * lk;
                if (key0 > q_lo)     s_[nt][0] = -1e30f;
                if (key0 + 1 > q_lo) s_[nt][1] = -1e30f;
                if (key0 > q_hi)     s_[nt][2] = -1e30f;
                if (key0 + 1 > q_hi) s_[nt][3] = -1e30f;
            }
        }

        const int r_lo = m_base + lq4, r_hi = r_lo + 8;
        float mx0 = -1e30f, mx1 = -1e30f;
#pragma unroll
        for (int nt = 0; nt < 8; nt++) {
            mx0 = fmaxf(mx0, fmaxf(s_[nt][0], s_[nt][1]));
            mx1 = fmaxf(mx1, fmaxf(s_[nt][2], s_[nt][3]));
        }
        mx0 = fmaxf(mx0, __shfl_xor_sync(0xffffffffu, mx0, 1));
        mx0 = fmaxf(mx0, __shfl_xor_sync(0xffffffffu, mx0, 2));
        mx1 = fmaxf(mx1, __shfl_xor_sync(0xffffffffu, mx1, 1));
        mx1 = fmaxf(mx1, __shfl_xor_sync(0xffffffffu, mx1, 2));
        if (lk == 0) {
            sRm[warp_n * 64 + r_lo] = mx0;
            sRm[warp_n * 64 + r_hi] = mx1;
        }
        __syncthreads();

        if (!last) { loadK(ks + 128); CPA_COMMIT(); }

        float m_lo = sMv[r_lo], m_hi = sMv[r_hi];
        float mn_lo = fmaxf(m_lo, fmaxf(sRm[r_lo], sRm[64 + r_lo]));
        float mn_hi = fmaxf(m_hi, fmaxf(sRm[r_hi], sRm[64 + r_hi]));
        float al_lo = ex2f(m_lo - mn_lo);
        float al_hi = ex2f(m_hi - mn_hi);

        float ps_lo = 0.f, ps_hi = 0.f;
#pragma unroll
        for (int nt = 0; nt < 8; nt++) {
            const int pi = warp_n * 32 + nt * 4 + lk;
            float p0 = ex2f(s_[nt][0] - mn_lo);
            float p1 = ex2f(s_[nt][1] - mn_lo);
            float p2 = ex2f(s_[nt][2] - mn_hi);
            float p3 = ex2f(s_[nt][3] - mn_hi);
            ps_lo += p0 + p1;
            ps_hi += p2 + p3;
            uint32_t hp, lp;
            split2(p0, p1, hp, lp);
            smu[O_PHI + r_lo * AST + pi] = hp;
            smu[O_PLO + r_lo * AST + pi] = lp;
            split2(p2, p3, hp, lp);
            smu[O_PHI + r_hi * AST + pi] = hp;
            smu[O_PLO + r_hi * AST + pi] = lp;
            o[nt][0] *= al_lo; o[nt][1] *= al_lo;
            o[nt][2] *= al_hi; o[nt][3] *= al_hi;
        }
        ps_lo += __shfl_xor_sync(0xffffffffu, ps_lo, 1);
        ps_lo += __shfl_xor_sync(0xffffffffu, ps_lo, 2);
        ps_hi += __shfl_xor_sync(0xffffffffu, ps_hi, 1);
        ps_hi += __shfl_xor_sync(0xffffffffu, ps_hi, 2);
        if (lk == 0) {
            sRl[warp_n * 64 + r_lo] = ps_lo;
            sRl[warp_n * 64 + r_hi] = ps_hi;
        }

        if (last) { CPA_WAIT0(); } else { CPA_WAIT1(); }
        __syncthreads();

        if (warp_n == 0 && lk == 0) {
            sLv[r_lo] = sLv[r_lo] * al_lo + sRl[r_lo] + sRl[64 + r_lo];
            sLv[r_hi] = sLv[r_hi] * al_hi + sRl[r_hi] + sRl[64 + r_hi];
            sMv[r_lo] = mn_lo;
            sMv[r_hi] = mn_hi;
        }

#pragma unroll
        for (int k8 = 0; k8 < 8; k8++) {
            const int base = k8 * 8 + lk;
            const uint32_t* ph = smu + O_PHI + (m_base + lq4) * AST;
            const uint32_t* pl = smu + O_PLO + (m_base + lq4) * AST;
            uint32_t ah[4] = {ph[base], ph[base + 8 * AST], ph[base + 4], ph[base + 8 * AST + 4]};
            uint32_t al[4] = {pl[base], pl[base + 8 * AST], pl[base + 4], pl[base + 8 * AST + 4]};
#pragma unroll
            for (int nt = 0; nt < 8; nt++) {
                const uint32_t* vh = smu + O_VHI + (n_base + nt * 8 + lq4) * AST;
                const uint32_t* vl = smu + O_VLO + (n_base + nt * 8 + lq4) * AST;
                uint32_t bh[2] = {vh[base], vh[base + 4]};
                uint32_t bl[2] = {vl[base], vl[base + 4]};
                mma16(o[nt], ah, bh);
                mma16(o[nt], ah, bl);
                mma16(o[nt], al, bh);
            }
        }

        if (!last) {
            __syncthreads();
            loadV(ks + 128);
            CPA_COMMIT();
        }
    }

    __syncthreads();
    const int base = ((b * 32 + qt) * 4 + chunk) * 64;
#pragma unroll
    for (int h = 0; h < 2; h++) {
        const int row = m_base + lq4 + 8 * h;
#pragma unroll
        for (int nt = 0; nt < 8; nt++) {
            const int col = n_base + nt * 8 + 2 * lk;
            *(float2*)&g_Op[(size_t)(base + row) * DH + col] =
                make_float2(o[nt][2 * h], o[nt][2 * h + 1]);
        }
    }
    if (tid < 64) {
        g_m[base + tid] = sMv[tid];
        g_l[base + tid] = sLv[tid];
    }
}

// ---------------------------------------------------------------------------
// Combine: grid (32 qt, 4 b, 2 q-halves), 256 thr; thread = 16 d of one q row.
// ---------------------------------------------------------------------------
__global__ __launch_bounds__(256) void attn_combine(float* __restrict__ out)
{
    const int qt = blockIdx.x, b = blockIdx.y;
    const int tid = threadIdx.x;
    const int q = blockIdx.z * 32 + (tid >> 3);
    const int d0 = (tid & 7) * 16;
    const int nch = qt / 8 + 1;
    const int base = (b * 32 + qt) * 256 + q;   // chunk stride = 64

    float mm[4];
    int cc[4];
#pragma unroll
    for (int c = 0; c < 4; c++) {
        cc[c] = (c < nch) ? c : (nch - 1);
        mm[c] = g_m[base + cc[c] * 64];
    }
    float M = fmaxf(fmaxf(mm[0], mm[1]), fmaxf(mm[2], mm[3]));
    float ww[4], L = 0.f;
#pragma unroll
    for (int c = 0; c < 4; c++) {
        ww[c] = (c < nch) ? ex2f(mm[c] - M) : 0.f;
        L += ww[c] * g_l[base + cc[c] * 64];
    }
    const float inv = 1.f / L;

    float* op = out + (size_t)(b * TSEQ + qt * 64 + q) * DH + d0;
#pragma unroll
    for (int d = 0; d < 16; d += 4) {
        float4 a = make_float4(0.f, 0.f, 0.f, 0.f);
#pragma unroll
        for (int c = 0; c < 4; c++) {
            const float4 v = *(const float4*)(g_Op + (size_t)(base + cc[c] * 64) * DH + d0 + d);
            a.x += ww[c] * v.x; a.y += ww[c] * v.y;
            a.z += ww[c] * v.z; a.w += ww[c] * v.w;
        }
        a.x *= inv; a.y *= inv; a.z *= inv; a.w *= inv;
        *(float4*)(op + d) = a;
    }
}

// ---------------------------------------------------------------------------
extern "C" void kernel_launch(void* const* d_in, const int* in_sizes, int n_in,
                              void* d_out, int out_size)
{
    const float* x     = (const float*)d_in[0];
    const float* Wq    = (const float*)d_in[1];
    const float* Wk    = (const float*)d_in[2];
    const float* Wv    = (const float*)d_in[3];
    const float* theta = (const float*)d_in[4];
    float* out = (float*)d_out;

    cudaFuncSetAttribute(qkv_mma, cudaFuncAttributeMaxDynamicSharedMemorySize, QKV_SMEM);
    cudaFuncSetAttribute(attn_part, cudaFuncAttributeMaxDynamicSharedMemorySize, AT_SMEM);

    rope_table<<<TSEQ, 128>>>(theta);
    convert_inputs<<<(NX8 + 3 * NW8) / 256, 256>>>(x, Wq, Wk, Wv);

    dim3 g1(NTOK / 128, 3);
    qkv_mma<<<g1, 256, QKV_SMEM>>>(0);

    attn_part<<<320, 256, AT_SMEM>>>(0);

    dim3 g3(32, 4, 2);
    attn_combine<<<g3, 256>>>(out);
}

// round 10
// speedup vs baseline: 28.4798x; 1.0736x over previous
#include <cuda_runtime.h>
#include <cuda_bf16.h>
#include <math.h>
#include <stdint.h>

#define TSEQ   2048
#define NTOK   8192
#define DM     1024
#define DH     128
#define QSCALE 0.03125f                 // 1/sqrt(1024)
#define LOG2E  1.4426950408889634f

// bf16 hi/lo planes of inputs (pre-converted once per launch)
__device__ unsigned short g_Xhi[NTOK * DM], g_Xlo[NTOK * DM];
__device__ unsigned short g_Whi[3 * DH * DM], g_Wlo[3 * DH * DM];
// Q,K token-major bf16 hi/lo planes; Vt transposed [DH][NTOK] planes.
__device__ unsigned short g_Qhi[NTOK * DH], g_Qlo[NTOK * DH];
__device__ unsigned short g_Khi[NTOK * DH], g_Klo[NTOK * DH];
__device__ unsigned short g_Vthi[DH * NTOK], g_Vtlo[DH * NTOK];
__device__ float g_ctab[TSEQ * DH];
__device__ float g_stab[TSEQ * DH];
// split-K partials: [b][qt][chunk][64 q][128 d]; m/l in log2 units
__device__ float g_Op[4 * 32 * 4 * 64 * DH];
__device__ float g_m [4 * 32 * 4 * 64];
__device__ float g_l [4 * 32 * 4 * 64];

__device__ __forceinline__ float ex2f(float x) {
    float y; asm("ex2.approx.ftz.f32 %0, %1;" : "=f"(y) : "f"(x)); return y;
}
__device__ __forceinline__ uint32_t s2u(const void* p) {
    uint32_t a;
    asm("{ .reg .u64 t; cvta.to.shared.u64 t, %1; cvt.u32.u64 %0, t; }"
        : "=r"(a) : "l"(p));
    return a;
}
#define CPA16(dst, src) \
    asm volatile("cp.async.cg.shared.global [%0], [%1], 16;" :: "r"(dst), "l"(src) : "memory")
#define CPA_COMMIT() asm volatile("cp.async.commit_group;" ::: "memory")
#define CPA_WAIT0()  asm volatile("cp.async.wait_group 0;" ::: "memory")
#define CPA_WAIT1()  asm volatile("cp.async.wait_group 1;" ::: "memory")

// bf16 m16n8k16 HMMA
__device__ __forceinline__ void mma16(float* c, const uint32_t* a, const uint32_t* b) {
    asm volatile(
        "mma.sync.aligned.m16n8k16.row.col.f32.bf16.bf16.f32 "
        "{%0,%1,%2,%3}, {%4,%5,%6,%7}, {%8,%9}, {%0,%1,%2,%3};"
        : "+f"(c[0]), "+f"(c[1]), "+f"(c[2]), "+f"(c[3])
        : "r"(a[0]), "r"(a[1]), "r"(a[2]), "r"(a[3]), "r"(b[0]), "r"(b[1]));
}

__device__ __forceinline__ void split2(float f0, float f1, uint32_t& hi, uint32_t& lo) {
    __nv_bfloat16 h0 = __float2bfloat16(f0);
    __nv_bfloat16 h1 = __float2bfloat16(f1);
    __nv_bfloat16 l0 = __float2bfloat16(f0 - __bfloat162float(h0));
    __nv_bfloat16 l1 = __float2bfloat16(f1 - __bfloat162float(h1));
    hi = (uint32_t)__bfloat16_as_ushort(h0) | ((uint32_t)__bfloat16_as_ushort(h1) << 16);
    lo = (uint32_t)__bfloat16_as_ushort(l0) | ((uint32_t)__bfloat16_as_ushort(l1) << 16);
}

// ---------------------------------------------------------------------------
__global__ __launch_bounds__(128) void rope_table(const float* __restrict__ theta) {
    int p = blockIdx.x, n = threadIdx.x;
    float s, c;
    sincosf((float)(p + 1) * theta[n], &s, &c);
    g_ctab[p * DH + n] = c;
    g_stab[p * DH + n] = s;
}

// ---------------------------------------------------------------------------
// Pre-convert x and Wq/Wk/Wv to bf16 hi/lo planes.  8 floats per thread.
// ---------------------------------------------------------------------------
#define NX8 (NTOK * DM / 8)            // 1048576
#define NW8 (DH * DM / 8)              // 16384
__global__ __launch_bounds__(256) void convert_inputs(
    const float* __restrict__ x,  const float* __restrict__ Wq,
    const float* __restrict__ Wk, const float* __restrict__ Wv)
{
    size_t gid = (size_t)blockIdx.x * 256 + threadIdx.x;
    const float* src;
    unsigned short *dhi, *dlo;
    size_t e0;
    if (gid < NX8) {
        src = x; dhi = g_Xhi; dlo = g_Xlo; e0 = gid * 8;
    } else {
        size_t r = gid - NX8;
        int mat = (int)(r / NW8);
        size_t rr = r - (size_t)mat * NW8;
        src = (mat == 0) ? Wq : ((mat == 1) ? Wk : Wv);
        dhi = g_Whi + (size_t)mat * DH * DM;
        dlo = g_Wlo + (size_t)mat * DH * DM;
        e0 = rr * 8;
    }
    float4 a = *(const float4*)(src + e0);
    float4 b = *(const float4*)(src + e0 + 4);
    uint32_t hp[4], lp[4];
    split2(a.x, a.y, hp[0], lp[0]);
    split2(a.z, a.w, hp[1], lp[1]);
    split2(b.x, b.y, hp[2], lp[2]);
    split2(b.z, b.w, hp[3], lp[3]);
    *(uint4*)(dhi + e0) = make_uint4(hp[0], hp[1], hp[2], hp[3]);
    *(uint4*)(dlo + e0) = make_uint4(lp[0], lp[1], lp[2], lp[3]);
}

// ---------------------------------------------------------------------------
// QKV projection, bf16x3 mma, 2-stage cp.async pipeline, M=64 tiles.
// grid (128 token-tiles, 3 mats), 256 thr (8 warps = 2m x 4n), 3 CTAs/SM.
// ---------------------------------------------------------------------------
#define QS 20
#define QO_XHI 0
#define QO_XLO (64 * QS)
#define QO_WHI (2 * 64 * QS)
#define QO_WLO (2 * 64 * QS + 128 * QS)
#define QSTG   (2 * 64 * QS + 2 * 128 * QS)   // 7680 u32 per stage
#define QKV_SMEM (2 * QSTG * 4)               // 61440 bytes

__global__ __launch_bounds__(256, 3)
void qkv_mma(int dummy) {
    extern __shared__ uint32_t qsm[];
    const uint32_t sbq = s2u(qsm);

    const int tid = threadIdx.x;
    const int lane = tid & 31, wid = tid >> 5;
    const int warp_m = wid & 1, warp_n = wid >> 1;     // 2m x 4n
    const int m_base = warp_m * 32, n_base = warp_n * 32;
    const int lq4 = lane >> 2, lk = lane & 3;
    const int t0 = blockIdx.x * 64;
    const int mat = blockIdx.y;

    const unsigned short* wHi = g_Whi + (size_t)mat * DH * DM;
    const unsigned short* wLo = g_Wlo + (size_t)mat * DH * DM;

    const int lrow = tid >> 2, lq = tid & 3;       // X: 64 rows x 4 quarters (8 elems)
    const int wrow = tid >> 1, whalf = tid & 1;    // W: 128 rows x 2 halves (16 elems)

    auto loadChunk = [&](int ci, int st) {
        const size_t xb = ((size_t)(t0 + lrow) * DM + ci * 32 + lq * 8) * 2;
        const size_t wb = ((size_t)wrow * DM + ci * 32 + whalf * 16) * 2;
        const uint32_t s0 = sbq + st * (QSTG * 4);
        const uint32_t dx = s0 + (lrow * QS + lq * 4) * 4;
        const uint32_t dw = s0 + (wrow * QS + whalf * 8) * 4;
        CPA16(dx + QO_XHI * 4,      (const char*)g_Xhi + xb);
        CPA16(dx + QO_XLO * 4,      (const char*)g_Xlo + xb);
        CPA16(dw + QO_WHI * 4,      (const char*)wHi + wb);
        CPA16(dw + QO_WHI * 4 + 16, (const char*)wHi + wb + 16);
        CPA16(dw + QO_WLO * 4,      (const char*)wLo + wb);
        CPA16(dw + QO_WLO * 4 + 16, (const char*)wLo + wb + 16);
    };

    float acc[2][4][4];
#pragma unroll
    for (int i = 0; i < 2; i++)
#pragma unroll
        for (int j = 0; j < 4; j++)
#pragma unroll
            for (int k = 0; k < 4; k++) acc[i][j][k] = 0.f;

    loadChunk(0, 0);
    CPA_COMMIT();

    for (int ci = 0; ci < 32; ci++) {
        if (ci + 1 < 32) {
            loadChunk(ci + 1, (ci + 1) & 1);
            CPA_COMMIT();
            CPA_WAIT1();
        } else {
            CPA_WAIT0();
        }
        __syncthreads();

        const uint32_t* st = qsm + (ci & 1) * QSTG;
#pragma unroll
        for (int kk = 0; kk < 2; kk++) {
            const int base = kk * 8 + lk;
            uint32_t ah[2][4], al[2][4];
#pragma unroll
            for (int mt = 0; mt < 2; mt++) {
                const uint32_t* ph = st + QO_XHI + (m_base + mt * 16 + lq4) * QS;
                const uint32_t* pl = st + QO_XLO + (m_base + mt * 16 + lq4) * QS;
                ah[mt][0] = ph[base];     ah[mt][1] = ph[base + 8 * QS];
                ah[mt][2] = ph[base + 4]; ah[mt][3] = ph[base + 8 * QS + 4];
                al[mt][0] = pl[base];     al[mt][1] = pl[base + 8 * QS];
                al[mt][2] = pl[base + 4]; al[mt][3] = pl[base + 8 * QS + 4];
            }
#pragma unroll
            for (int nt = 0; nt < 4; nt++) {
                const uint32_t* ph = st + QO_WHI + (n_base + nt * 8 + lq4) * QS;
                const uint32_t* pl = st + QO_WLO + (n_base + nt * 8 + lq4) * QS;
                uint32_t bh[2] = {ph[base], ph[base + 4]};
                uint32_t bl[2] = {pl[base], pl[base + 4]};
#pragma unroll
                for (int mt = 0; mt < 2; mt++) {
                    mma16(acc[mt][nt], ah[mt], bh);
                    mma16(acc[mt][nt], ah[mt], bl);
                    mma16(acc[mt][nt], al[mt], bh);
                }
            }
        }
        __syncthreads();
    }

    // ---- epilogue ----
    if (mat < 2) {
        const float sc = (mat == 0) ? (QSCALE * LOG2E) : 1.f;
        unsigned short* dhi = (mat == 0) ? g_Qhi : g_Khi;
        unsigned short* dlo = (mat == 0) ? g_Qlo : g_Klo;
#pragma unroll
        for (int mt = 0; mt < 2; mt++)
#pragma unroll
            for (int h = 0; h < 2; h++) {
                const int tok = t0 + m_base + mt * 16 + lq4 + 8 * h;
                const int pos = tok & (TSEQ - 1);
#pragma unroll
                for (int nt = 0; nt < 4; nt++) {
                    const int colE = n_base + nt * 8 + 2 * lk;
                    float e = acc[mt][nt][2 * h] * sc;
                    float o = acc[mt][nt][2 * h + 1] * sc;
                    float ct = g_ctab[pos * DH + colE];
                    float st = g_stab[pos * DH + colE];
                    float re = e * ct + o * st;
                    float ro = o * ct - e * st;
                    uint32_t hi, lo;
                    split2(re, ro, hi, lo);
                    *(uint32_t*)&dhi[(size_t)tok * DH + colE] = hi;
                    *(uint32_t*)&dlo[(size_t)tok * DH + colE] = lo;
                }
            }
    } else {
#pragma unroll
        for (int mt = 0; mt < 2; mt++)
#pragma unroll
            for (int h = 0; h < 2; h++) {
                const int tok = t0 + m_base + mt * 16 + lq4 + 8 * h;
#pragma unroll
                for (int nt = 0; nt < 4; nt++) {
                    const int colE = n_base + nt * 8 + 2 * lk;
#pragma unroll
                    for (int e = 0; e < 2; e++) {
                        float v = acc[mt][nt][2 * h + e];
                        __nv_bfloat16 hb = __float2bfloat16(v);
                        __nv_bfloat16 lb = __float2bfloat16(v - __bfloat162float(hb));
                        g_Vthi[(size_t)(colE + e) * NTOK + tok] = __bfloat16_as_ushort(hb);
                        g_Vtlo[(size_t)(colE + e) * NTOK + tok] = __bfloat16_as_ushort(lb);
                    }
                }
            }
    }
}

// ---------------------------------------------------------------------------
// Flash attention partials, bf16x3 mma, pipelined K/V, 512 threads (16 warps:
// 4m x 4n; warp_n owns a 32-col slice).  320 blocks.
// ---------------------------------------------------------------------------
#define AST 68
#define O_QHI 0
#define O_QLO (O_QHI + 64 * AST)
#define O_KHI (O_QLO + 64 * AST)
#define O_KLO (O_KHI + 128 * AST)
#define O_VHI (O_KLO + 128 * AST)
#define O_VLO (O_VHI + 128 * AST)
#define O_PHI (O_VLO + 128 * AST)
#define O_PLO (O_PHI + 64 * AST)
#define O_F   (O_PLO + 64 * AST)
#define AT_SMEM ((O_F + 64 + 64 + 256 + 256) * 4)

__global__ __launch_bounds__(512, 1) void attn_part(int dummy)
{
    extern __shared__ uint32_t smu[];
    float* sMv = (float*)(smu + O_F);
    float* sLv = sMv + 64;
    float* sRm = sLv + 64;      // [4][64]
    float* sRl = sRm + 256;     // [4][64]
    const uint32_t sb = s2u(smu);

    const int tid = threadIdx.x;
    const int lane = tid & 31, wid = tid >> 5;
    const int warp_m = wid & 3, warp_n = wid >> 2;   // 4m x 4n
    const int m_base = warp_m * 16, n_base = warp_n * 32;
    const int lq4 = lane >> 2, lk = lane & 3;

    int r = blockIdx.x % 80;
    int b = blockIdx.x / 80;
    int qt, chunk;
    if (r < 8)       { qt = r;                 chunk = 0; }
    else if (r < 24) { qt = 8  + (r - 8) / 2;  chunk = (r - 8) % 2; }
    else if (r < 48) { qt = 16 + (r - 24) / 3; chunk = (r - 24) % 3; }
    else             { qt = 24 + (r - 48) / 4; chunk = (r - 48) % 4; }

    const int q0   = qt * 64;
    const int kbeg = chunk * 512;
    const int kend = min(q0 + 64, kbeg + 512);
    const int tokb = b * TSEQ;

    auto loadK = [&](int ks_) {
#pragma unroll
        for (int it = 0; it < 4; it++) {
            int idx = tid + 512 * it;
            int row = idx >> 4, c = idx & 15;
            CPA16(sb + (O_KHI + row * AST + c * 4) * 4,
                  (const char*)g_Khi + ((size_t)(tokb + ks_ + row) * DH + c * 8) * 2);
            CPA16(sb + (O_KLO + row * AST + c * 4) * 4,
                  (const char*)g_Klo + ((size_t)(tokb + ks_ + row) * DH + c * 8) * 2);
        }
    };
    auto loadV = [&](int ks_) {
#pragma unroll
        for (int it = 0; it < 4; it++) {
            int idx = tid + 512 * it;
            int row = idx >> 4, c = idx & 15;
            CPA16(sb + (O_VHI + row * AST + c * 4) * 4,
                  (const char*)g_Vthi + ((size_t)row * NTOK + tokb + ks_ + c * 8) * 2);
            CPA16(sb + (O_VLO + row * AST + c * 4) * 4,
                  (const char*)g_Vtlo + ((size_t)row * NTOK + tokb + ks_ + c * 8) * 2);
        }
    };

    // group0: Q + K0    group1: V0
#pragma unroll
    for (int it = 0; it < 2; it++) {
        int idx = tid + 512 * it;
        int row = idx >> 4, c = idx & 15;
        CPA16(sb + (O_QHI + row * AST + c * 4) * 4,
              (const char*)g_Qhi + ((size_t)(tokb + q0 + row) * DH + c * 8) * 2);
        CPA16(sb + (O_QLO + row * AST + c * 4) * 4,
              (const char*)g_Qlo + ((size_t)(tokb + q0 + row) * DH + c * 8) * 2);
    }
    loadK(kbeg);
    CPA_COMMIT();
    loadV(kbeg);
    CPA_COMMIT();

    if (tid < 64) { sMv[tid] = -1e30f; sLv[tid] = 0.f; }

    float o[4][4];
#pragma unroll
    for (int j = 0; j < 4; j++)
#pragma unroll
        for (int k = 0; k < 4; k++) o[j][k] = 0.f;

    for (int ks = kbeg; ks < kend; ks += 128) {
        const bool last = (ks + 128 >= kend);
        CPA_WAIT1();
        __syncthreads();

        // ---- S = Q K^T ----
        float s_[4][4];
#pragma unroll
        for (int j = 0; j < 4; j++)
#pragma unroll
            for (int k = 0; k < 4; k++) s_[j][k] = 0.f;
#pragma unroll
        for (int k8 = 0; k8 < 8; k8++) {
            const int base = k8 * 8 + lk;
            const uint32_t* qh = smu + O_QHI + (m_base + lq4) * AST;
            const uint32_t* ql = smu + O_QLO + (m_base + lq4) * AST;
            uint32_t ah[4] = {qh[base], qh[base + 8 * AST], qh[base + 4], qh[base + 8 * AST + 4]};
            uint32_t al[4] = {ql[base], ql[base + 8 * AST], ql[base + 4], ql[base + 8 * AST + 4]};
#pragma unroll
            for (int nt = 0; nt < 4; nt++) {
                const uint32_t* kh = smu + O_KHI + (n_base + nt * 8 + lq4) * AST;
                const uint32_t* kl = smu + O_KLO + (n_base + nt * 8 + lq4) * AST;
                uint32_t bh[2] = {kh[base], kh[base + 4]};
                uint32_t bl[2] = {kl[base], kl[base + 4]};
                mma16(s_[nt], ah, bh);
                mma16(s_[nt], ah, bl);
                mma16(s_[nt], al, bh);
            }
        }

        // ---- causal mask ----
        if (ks + 128 > q0) {
            const int q_lo = q0 + m_base + lq4, q_hi = q_lo + 8;
#pragma unroll
            for (int nt = 0; nt < 4; nt++) {
                const int key0 = ks + n_base + nt * 8 + 2 * lk;
                if (key0 > q_lo)     s_[nt][0] = -1e30f;
                if (key0 + 1 > q_lo) s_[nt][1] = -1e30f;
                if (key0 > q_hi)     s_[nt][2] = -1e30f;
                if (key0 + 1 > q_hi) s_[nt][3] = -1e30f;
            }
        }

        // ---- online softmax (log2 units) ----
        const int r_lo = m_base + lq4, r_hi = r_lo + 8;
        float mx0 = -1e30f, mx1 = -1e30f;
#pragma unroll
        for (int nt = 0; nt < 4; nt++) {
            mx0 = fmaxf(mx0, fmaxf(s_[nt][0], s_[nt][1]));
            mx1 = fmaxf(mx1, fmaxf(s_[nt][2], s_[nt][3]));
        }
        mx0 = fmaxf(mx0, __shfl_xor_sync(0xffffffffu, mx0, 1));
        mx0 = fmaxf(mx0, __shfl_xor_sync(0xffffffffu, mx0, 2));
        mx1 = fmaxf(mx1, __shfl_xor_sync(0xffffffffu, mx1, 1));
        mx1 = fmaxf(mx1, __shfl_xor_sync(0xffffffffu, mx1, 2));
        if (lk == 0) {
            sRm[warp_n * 64 + r_lo] = mx0;
            sRm[warp_n * 64 + r_hi] = mx1;
        }
        __syncthreads();           // all warps past S reads -> K buffer free

        if (!last) { loadK(ks + 128); CPA_COMMIT(); }

        float m_lo = sMv[r_lo], m_hi = sMv[r_hi];
        float mn_lo = fmaxf(fmaxf(m_lo, fmaxf(sRm[r_lo], sRm[64 + r_lo])),
                            fmaxf(sRm[128 + r_lo], sRm[192 + r_lo]));
        float mn_hi = fmaxf(fmaxf(m_hi, fmaxf(sRm[r_hi], sRm[64 + r_hi])),
                            fmaxf(sRm[128 + r_hi], sRm[192 + r_hi]));
        float al_lo = ex2f(m_lo - mn_lo);
        float al_hi = ex2f(m_hi - mn_hi);

        float ps_lo = 0.f, ps_hi = 0.f;
#pragma unroll
        for (int nt = 0; nt < 4; nt++) {
            const int pi = warp_n * 16 + nt * 4 + lk;
            float p0 = ex2f(s_[nt][0] - mn_lo);
            float p1 = ex2f(s_[nt][1] - mn_lo);
            float p2 = ex2f(s_[nt][2] - mn_hi);
            float p3 = ex2f(s_[nt][3] - mn_hi);
            ps_lo += p0 + p1;
            ps_hi += p2 + p3;
            uint32_t hp, lp;
            split2(p0, p1, hp, lp);
            smu[O_PHI + r_lo * AST + pi] = hp;
            smu[O_PLO + r_lo * AST + pi] = lp;
            split2(p2, p3, hp, lp);
            smu[O_PHI + r_hi * AST + pi] = hp;
            smu[O_PLO + r_hi * AST + pi] = lp;
            o[nt][0] *= al_lo; o[nt][1] *= al_lo;
            o[nt][2] *= al_hi; o[nt][3] *= al_hi;
        }
        ps_lo += __shfl_xor_sync(0xffffffffu, ps_lo, 1);
        ps_lo += __shfl_xor_sync(0xffffffffu, ps_lo, 2);
        ps_hi += __shfl_xor_sync(0xffffffffu, ps_hi, 1);
        ps_hi += __shfl_xor_sync(0xffffffffu, ps_hi, 2);
        if (lk == 0) {
            sRl[warp_n * 64 + r_lo] = ps_lo;
            sRl[warp_n * 64 + r_hi] = ps_hi;
        }

        if (last) { CPA_WAIT0(); } else { CPA_WAIT1(); }
        __syncthreads();

        if (warp_n == 0 && lk == 0) {
            sLv[r_lo] = sLv[r_lo] * al_lo + sRl[r_lo] + sRl[64 + r_lo]
                        + sRl[128 + r_lo] + sRl[192 + r_lo];
            sLv[r_hi] = sLv[r_hi] * al_hi + sRl[r_hi] + sRl[64 + r_hi]
                        + sRl[128 + r_hi] + sRl[192 + r_hi];
            sMv[r_lo] = mn_lo;
            sMv[r_hi] = mn_hi;
        }

        // ---- O += P V ----
#pragma unroll
        for (int k8 = 0; k8 < 8; k8++) {
            const int base = k8 * 8 + lk;
            const uint32_t* ph = smu + O_PHI + (m_base + lq4) * AST;
            const uint32_t* pl = smu + O_PLO + (m_base + lq4) * AST;
            uint32_t ah[4] = {ph[base], ph[base + 8 * AST], ph[base + 4], ph[base + 8 * AST + 4]};
            uint32_t al[4] = {pl[base], pl[base + 8 * AST], pl[base + 4], pl[base + 8 * AST + 4]};
#pragma unroll
            for (int nt = 0; nt < 4; nt++) {
                const uint32_t* vh = smu + O_VHI + (n_base + nt * 8 + lq4) * AST;
                const uint32_t* vl = smu + O_VLO + (n_base + nt * 8 + lq4) * AST;
                uint32_t bh[2] = {vh[base], vh[base + 4]};
                uint32_t bl[2] = {vl[base], vl[base + 4]};
                mma16(o[nt], ah, bh);
                mma16(o[nt], ah, bl);
                mma16(o[nt], al, bh);
            }
        }

        if (!last) {
            __syncthreads();
            loadV(ks + 128);
            CPA_COMMIT();
        }
    }

    __syncthreads();
    const int base = ((b * 32 + qt) * 4 + chunk) * 64;
#pragma unroll
    for (int h = 0; h < 2; h++) {
        const int row = m_base + lq4 + 8 * h;
#pragma unroll
        for (int nt = 0; nt < 4; nt++) {
            const int col = n_base + nt * 8 + 2 * lk;
            *(float2*)&g_Op[(size_t)(base + row) * DH + col] =
                make_float2(o[nt][2 * h], o[nt][2 * h + 1]);
        }
    }
    if (tid < 64) {
        g_m[base + tid] = sMv[tid];
        g_l[base + tid] = sLv[tid];
    }
}

// ---------------------------------------------------------------------------
// Combine: grid (32 qt, 4 b, 2 q-halves), 256 thr; thread = 16 d of one q row.
// ---------------------------------------------------------------------------
__global__ __launch_bounds__(256) void attn_combine(float* __restrict__ out)
{
    const int qt = blockIdx.x, b = blockIdx.y;
    const int tid = threadIdx.x;
    const int q = blockIdx.z * 32 + (tid >> 3);
    const int d0 = (tid & 7) * 16;
    const int nch = qt / 8 + 1;
    const int base = (b * 32 + qt) * 256 + q;   // chunk stride = 64

    float mm[4];
    int cc[4];
#pragma unroll
    for (int c = 0; c < 4; c++) {
        cc[c] = (c < nch) ? c : (nch - 1);
        mm[c] = g_m[base + cc[c] * 64];
    }
    float M = fmaxf(fmaxf(mm[0], mm[1]), fmaxf(mm[2], mm[3]));
    float ww[4], L = 0.f;
#pragma unroll
    for (int c = 0; c < 4; c++) {
        ww[c] = (c < nch) ? ex2f(mm[c] - M) : 0.f;
        L += ww[c] * g_l[base + cc[c] * 64];
    }
    const float inv = 1.f / L;

    float* op = out + (size_t)(b * TSEQ + qt * 64 + q) * DH + d0;
#pragma unroll
    for (int d = 0; d < 16; d += 4) {
        float4 a = make_float4(0.f, 0.f, 0.f, 0.f);
#pragma unroll
        for (int c = 0; c < 4; c++) {
            const float4 v = *(const float4*)(g_Op + (size_t)(base + cc[c] * 64) * DH + d0 + d);
            a.x += ww[c] * v.x; a.y += ww[c] * v.y;
            a.z += ww[c] * v.z; a.w += ww[c] * v.w;
        }
        a.x *= inv; a.y *= inv; a.z *= inv; a.w *= inv;
        *(float4*)(op + d) = a;
    }
}

// ---------------------------------------------------------------------------
extern "C" void kernel_launch(void* const* d_in, const int* in_sizes, int n_in,
                              void* d_out, int out_size)
{
    const float* x     = (const float*)d_in[0];
    const float* Wq    = (const float*)d_in[1];
    const float* Wk    = (const float*)d_in[2];
    const float* Wv    = (const float*)d_in[3];
    const float* theta = (const float*)d_in[4];
    float* out = (float*)d_out;

    cudaFuncSetAttribute(qkv_mma, cudaFuncAttributeMaxDynamicSharedMemorySize, QKV_SMEM);
    cudaFuncSetAttribute(attn_part, cudaFuncAttributeMaxDynamicSharedMemorySize, AT_SMEM);

    rope_table<<<TSEQ, 128>>>(theta);
    convert_inputs<<<(NX8 + 3 * NW8) / 256, 256>>>(x, Wq, Wk, Wv);

    dim3 g1(NTOK / 64, 3);
    qkv_mma<<<g1, 256, QKV_SMEM>>>(0);

    attn_part<<<320, 512, AT_SMEM>>>(0);

    dim3 g3(32, 4, 2);
    attn_combine<<<g3, 256>>>(out);
}

// round 11
// speedup vs baseline: 31.9259x; 1.1210x over previous
#include <cuda_runtime.h>
#include <cuda_bf16.h>
#include <math.h>
#include <stdint.h>

#define TSEQ   2048
#define NTOK   8192
#define DM     1024
#define DH     128
#define QSCALE 0.03125f                 // 1/sqrt(1024)
#define LOG2E  1.4426950408889634f

// bf16 hi/lo planes of inputs (pre-converted once per launch)
__device__ unsigned short g_Xhi[NTOK * DM], g_Xlo[NTOK * DM];
__device__ unsigned short g_Whi[3 * DH * DM], g_Wlo[3 * DH * DM];
// Q,K token-major bf16 hi/lo planes; Vt transposed [DH][NTOK] planes.
__device__ unsigned short g_Qhi[NTOK * DH], g_Qlo[NTOK * DH];
__device__ unsigned short g_Khi[NTOK * DH], g_Klo[NTOK * DH];
__device__ unsigned short g_Vthi[DH * NTOK], g_Vtlo[DH * NTOK];
__device__ float g_ctab[TSEQ * DH];
__device__ float g_stab[TSEQ * DH];
// split-K partials: [b][qt16][chunk8][128 q][128 d]; m/l in log2 units
__device__ float g_Op[4 * 16 * 8 * 128 * DH];
__device__ float g_m [4 * 16 * 8 * 128];
__device__ float g_l [4 * 16 * 8 * 128];

__device__ __forceinline__ float ex2f(float x) {
    float y; asm("ex2.approx.ftz.f32 %0, %1;" : "=f"(y) : "f"(x)); return y;
}
__device__ __forceinline__ uint32_t s2u(const void* p) {
    uint32_t a;
    asm("{ .reg .u64 t; cvta.to.shared.u64 t, %1; cvt.u32.u64 %0, t; }"
        : "=r"(a) : "l"(p));
    return a;
}
#define CPA16(dst, src) \
    asm volatile("cp.async.cg.shared.global [%0], [%1], 16;" :: "r"(dst), "l"(src) : "memory")
#define CPA_COMMIT() asm volatile("cp.async.commit_group;" ::: "memory")
#define CPA_WAIT0()  asm volatile("cp.async.wait_group 0;" ::: "memory")
#define CPA_WAIT1()  asm volatile("cp.async.wait_group 1;" ::: "memory")

// bf16 m16n8k16 HMMA
__device__ __forceinline__ void mma16(float* c, const uint32_t* a, const uint32_t* b) {
    asm volatile(
        "mma.sync.aligned.m16n8k16.row.col.f32.bf16.bf16.f32 "
        "{%0,%1,%2,%3}, {%4,%5,%6,%7}, {%8,%9}, {%0,%1,%2,%3};"
        : "+f"(c[0]), "+f"(c[1]), "+f"(c[2]), "+f"(c[3])
        : "r"(a[0]), "r"(a[1]), "r"(a[2]), "r"(a[3]), "r"(b[0]), "r"(b[1]));
}

__device__ __forceinline__ void split2(float f0, float f1, uint32_t& hi, uint32_t& lo) {
    __nv_bfloat16 h0 = __float2bfloat16(f0);
    __nv_bfloat16 h1 = __float2bfloat16(f1);
    __nv_bfloat16 l0 = __float2bfloat16(f0 - __bfloat162float(h0));
    __nv_bfloat16 l1 = __float2bfloat16(f1 - __bfloat162float(h1));
    hi = (uint32_t)__bfloat16_as_ushort(h0) | ((uint32_t)__bfloat16_as_ushort(h1) << 16);
    lo = (uint32_t)__bfloat16_as_ushort(l0) | ((uint32_t)__bfloat16_as_ushort(l1) << 16);
}

// ---------------------------------------------------------------------------
__global__ __launch_bounds__(128) void rope_table(const float* __restrict__ theta) {
    int p = blockIdx.x, n = threadIdx.x;
    float s, c;
    sincosf((float)(p + 1) * theta[n], &s, &c);
    g_ctab[p * DH + n] = c;
    g_stab[p * DH + n] = s;
}

// ---------------------------------------------------------------------------
// Pre-convert x and Wq/Wk/Wv to bf16 hi/lo planes.  8 floats per thread.
// ---------------------------------------------------------------------------
#define NX8 (NTOK * DM / 8)            // 1048576
#define NW8 (DH * DM / 8)              // 16384
__global__ __launch_bounds__(256) void convert_inputs(
    const float* __restrict__ x,  const float* __restrict__ Wq,
    const float* __restrict__ Wk, const float* __restrict__ Wv)
{
    size_t gid = (size_t)blockIdx.x * 256 + threadIdx.x;
    const float* src;
    unsigned short *dhi, *dlo;
    size_t e0;
    if (gid < NX8) {
        src = x; dhi = g_Xhi; dlo = g_Xlo; e0 = gid * 8;
    } else {
        size_t r = gid - NX8;
        int mat = (int)(r / NW8);
        size_t rr = r - (size_t)mat * NW8;
        src = (mat == 0) ? Wq : ((mat == 1) ? Wk : Wv);
        dhi = g_Whi + (size_t)mat * DH * DM;
        dlo = g_Wlo + (size_t)mat * DH * DM;
        e0 = rr * 8;
    }
    float4 a = *(const float4*)(src + e0);
    float4 b = *(const float4*)(src + e0 + 4);
    uint32_t hp[4], lp[4];
    split2(a.x, a.y, hp[0], lp[0]);
    split2(a.z, a.w, hp[1], lp[1]);
    split2(b.x, b.y, hp[2], lp[2]);
    split2(b.z, b.w, hp[3], lp[3]);
    *(uint4*)(dhi + e0) = make_uint4(hp[0], hp[1], hp[2], hp[3]);
    *(uint4*)(dlo + e0) = make_uint4(lp[0], lp[1], lp[2], lp[3]);
}

// ---------------------------------------------------------------------------
// QKV projection, bf16x3 mma, 2-stage cp.async pipeline, M=64 tiles.
// (unchanged from R10 passing version)
// ---------------------------------------------------------------------------
#define QS 20
#define QO_XHI 0
#define QO_XLO (64 * QS)
#define QO_WHI (2 * 64 * QS)
#define QO_WLO (2 * 64 * QS + 128 * QS)
#define QSTG   (2 * 64 * QS + 2 * 128 * QS)   // 7680 u32 per stage
#define QKV_SMEM (2 * QSTG * 4)               // 61440 bytes

__global__ __launch_bounds__(256, 3)
void qkv_mma(int dummy) {
    extern __shared__ uint32_t qsm[];
    const uint32_t sbq = s2u(qsm);

    const int tid = threadIdx.x;
    const int lane = tid & 31, wid = tid >> 5;
    const int warp_m = wid & 1, warp_n = wid >> 1;     // 2m x 4n
    const int m_base = warp_m * 32, n_base = warp_n * 32;
    const int lq4 = lane >> 2, lk = lane & 3;
    const int t0 = blockIdx.x * 64;
    const int mat = blockIdx.y;

    const unsigned short* wHi = g_Whi + (size_t)mat * DH * DM;
    const unsigned short* wLo = g_Wlo + (size_t)mat * DH * DM;

    const int lrow = tid >> 2, lq = tid & 3;       // X: 64 rows x 4 quarters
    const int wrow = tid >> 1, whalf = tid & 1;    // W: 128 rows x 2 halves

    auto loadChunk = [&](int ci, int st) {
        const size_t xb = ((size_t)(t0 + lrow) * DM + ci * 32 + lq * 8) * 2;
        const size_t wb = ((size_t)wrow * DM + ci * 32 + whalf * 16) * 2;
        const uint32_t s0 = sbq + st * (QSTG * 4);
        const uint32_t dx = s0 + (lrow * QS + lq * 4) * 4;
        const uint32_t dw = s0 + (wrow * QS + whalf * 8) * 4;
        CPA16(dx + QO_XHI * 4,      (const char*)g_Xhi + xb);
        CPA16(dx + QO_XLO * 4,      (const char*)g_Xlo + xb);
        CPA16(dw + QO_WHI * 4,      (const char*)wHi + wb);
        CPA16(dw + QO_WHI * 4 + 16, (const char*)wHi + wb + 16);
        CPA16(dw + QO_WLO * 4,      (const char*)wLo + wb);
        CPA16(dw + QO_WLO * 4 + 16, (const char*)wLo + wb + 16);
    };

    float acc[2][4][4];
#pragma unroll
    for (int i = 0; i < 2; i++)
#pragma unroll
        for (int j = 0; j < 4; j++)
#pragma unroll
            for (int k = 0; k < 4; k++) acc[i][j][k] = 0.f;

    loadChunk(0, 0);
    CPA_COMMIT();

    for (int ci = 0; ci < 32; ci++) {
        if (ci + 1 < 32) {
            loadChunk(ci + 1, (ci + 1) & 1);
            CPA_COMMIT();
            CPA_WAIT1();
        } else {
            CPA_WAIT0();
        }
        __syncthreads();

        const uint32_t* st = qsm + (ci & 1) * QSTG;
#pragma unroll
        for (int kk = 0; kk < 2; kk++) {
            const int base = kk * 8 + lk;
            uint32_t ah[2][4], al[2][4];
#pragma unroll
            for (int mt = 0; mt < 2; mt++) {
                const uint32_t* ph = st + QO_XHI + (m_base + mt * 16 + lq4) * QS;
                const uint32_t* pl = st + QO_XLO + (m_base + mt * 16 + lq4) * QS;
                ah[mt][0] = ph[base];     ah[mt][1] = ph[base + 8 * QS];
                ah[mt][2] = ph[base + 4]; ah[mt][3] = ph[base + 8 * QS + 4];
                al[mt][0] = pl[base];     al[mt][1] = pl[base + 8 * QS];
                al[mt][2] = pl[base + 4]; al[mt][3] = pl[base + 8 * QS + 4];
            }
#pragma unroll
            for (int nt = 0; nt < 4; nt++) {
                const uint32_t* ph = st + QO_WHI + (n_base + nt * 8 + lq4) * QS;
                const uint32_t* pl = st + QO_WLO + (n_base + nt * 8 + lq4) * QS;
                uint32_t bh[2] = {ph[base], ph[base + 4]};
                uint32_t bl[2] = {pl[base], pl[base + 4]};
#pragma unroll
                for (int mt = 0; mt < 2; mt++) {
                    mma16(acc[mt][nt], ah[mt], bh);
                    mma16(acc[mt][nt], ah[mt], bl);
                    mma16(acc[mt][nt], al[mt], bh);
                }
            }
        }
        __syncthreads();
    }

    if (mat < 2) {
        const float sc = (mat == 0) ? (QSCALE * LOG2E) : 1.f;
        unsigned short* dhi = (mat == 0) ? g_Qhi : g_Khi;
        unsigned short* dlo = (mat == 0) ? g_Qlo : g_Klo;
#pragma unroll
        for (int mt = 0; mt < 2; mt++)
#pragma unroll
            for (int h = 0; h < 2; h++) {
                const int tok = t0 + m_base + mt * 16 + lq4 + 8 * h;
                const int pos = tok & (TSEQ - 1);
#pragma unroll
                for (int nt = 0; nt < 4; nt++) {
                    const int colE = n_base + nt * 8 + 2 * lk;
                    float e = acc[mt][nt][2 * h] * sc;
                    float o = acc[mt][nt][2 * h + 1] * sc;
                    float ct = g_ctab[pos * DH + colE];
                    float st = g_stab[pos * DH + colE];
                    float re = e * ct + o * st;
                    float ro = o * ct - e * st;
                    uint32_t hi, lo;
                    split2(re, ro, hi, lo);
                    *(uint32_t*)&dhi[(size_t)tok * DH + colE] = hi;
                    *(uint32_t*)&dlo[(size_t)tok * DH + colE] = lo;
                }
            }
    } else {
#pragma unroll
        for (int mt = 0; mt < 2; mt++)
#pragma unroll
            for (int h = 0; h < 2; h++) {
                const int tok = t0 + m_base + mt * 16 + lq4 + 8 * h;
#pragma unroll
                for (int nt = 0; nt < 4; nt++) {
                    const int colE = n_base + nt * 8 + 2 * lk;
#pragma unroll
                    for (int e = 0; e < 2; e++) {
                        float v = acc[mt][nt][2 * h + e];
                        __nv_bfloat16 hb = __float2bfloat16(v);
                        __nv_bfloat16 lb = __float2bfloat16(v - __bfloat162float(hb));
                        g_Vthi[(size_t)(colE + e) * NTOK + tok] = __bfloat16_as_ushort(hb);
                        g_Vtlo[(size_t)(colE + e) * NTOK + tok] = __bfloat16_as_ushort(lb);
                    }
                }
            }
    }
}

// ---------------------------------------------------------------------------
// Flash attention partials — FA2 style, register-resident P.
// 288 blocks x 256 threads (8 warps).  Block = (batch, 128-q tile, 256-key
// chunk).  Warp owns 16 q rows x ALL 128 keys: softmax is warp-local (no smem
// reductions, no P staging).  3 syncs per 128-key tile.
// ---------------------------------------------------------------------------
#define AST 68
#define O_QHI 0
#define O_QLO (O_QHI + 128 * AST)
#define O_KHI (O_QLO + 128 * AST)
#define O_KLO (O_KHI + 128 * AST)
#define O_VHI (O_KLO + 128 * AST)
#define O_VLO (O_VHI + 128 * AST)
#define AT_SMEM ((O_VLO + 128 * AST) * 4)    // 208896 bytes

__global__ __launch_bounds__(256, 1) void attn_part(int dummy)
{
    extern __shared__ uint32_t smu[];
    const uint32_t sb = s2u(smu);

    const int tid = threadIdx.x;
    const int lane = tid & 31, wid = tid >> 5;   // 8 warps
    const int m_base = wid * 16;
    const int lq4 = lane >> 2, lk = lane & 3;

    // block -> (b, qt, chunk):  qt in [0,16), chunks of 256 keys, nch=(qt+2)/2
    int rr = blockIdx.x % 72;
    int b  = blockIdx.x / 72;
    int qt = 0, chunk = rr;
    for (int i = 0; i < 16; i++) {
        int cnt = (i + 2) >> 1;
        if (chunk < cnt) { qt = i; break; }
        chunk -= cnt;
    }

    const int q0   = qt * 128;
    const int kbeg = chunk * 256;
    const int kend = min(q0 + 128, kbeg + 256);
    const int tokb = b * TSEQ;

    auto loadK = [&](int ks_) {
#pragma unroll
        for (int it = 0; it < 8; it++) {
            int idx = tid + 256 * it;
            int row = idx >> 4, c = idx & 15;
            CPA16(sb + (O_KHI + row * AST + c * 4) * 4,
                  (const char*)g_Khi + ((size_t)(tokb + ks_ + row) * DH + c * 8) * 2);
            CPA16(sb + (O_KLO + row * AST + c * 4) * 4,
                  (const char*)g_Klo + ((size_t)(tokb + ks_ + row) * DH + c * 8) * 2);
        }
    };
    auto loadV = [&](int ks_) {
#pragma unroll
        for (int it = 0; it < 8; it++) {
            int idx = tid + 256 * it;
            int row = idx >> 4, c = idx & 15;
            CPA16(sb + (O_VHI + row * AST + c * 4) * 4,
                  (const char*)g_Vthi + ((size_t)row * NTOK + tokb + ks_ + c * 8) * 2);
            CPA16(sb + (O_VLO + row * AST + c * 4) * 4,
                  (const char*)g_Vtlo + ((size_t)row * NTOK + tokb + ks_ + c * 8) * 2);
        }
    };

    // group0: Q + K0    group1: V0
#pragma unroll
    for (int it = 0; it < 8; it++) {
        int idx = tid + 256 * it;
        int row = idx >> 4, c = idx & 15;
        CPA16(sb + (O_QHI + row * AST + c * 4) * 4,
              (const char*)g_Qhi + ((size_t)(tokb + q0 + row) * DH + c * 8) * 2);
        CPA16(sb + (O_QLO + row * AST + c * 4) * 4,
              (const char*)g_Qlo + ((size_t)(tokb + q0 + row) * DH + c * 8) * 2);
    }
    loadK(kbeg);
    CPA_COMMIT();
    loadV(kbeg);
    CPA_COMMIT();

    float m_lo = -1e30f, m_hi = -1e30f, l_lo = 0.f, l_hi = 0.f;
    float o_[16][4];
#pragma unroll
    for (int j = 0; j < 16; j++)
#pragma unroll
        for (int k = 0; k < 4; k++) o_[j][k] = 0.f;

    for (int ks = kbeg; ks < kend; ks += 128) {
        const bool last = (ks + 128 >= kend);
        CPA_WAIT1();               // Q+K_cur resident; V_cur may be in flight
        __syncthreads();

        // ---- S = Q K^T : warp covers 16 rows x 128 keys (16 n8 tiles) ----
        float s_[16][4];
#pragma unroll
        for (int j = 0; j < 16; j++)
#pragma unroll
            for (int k = 0; k < 4; k++) s_[j][k] = 0.f;
#pragma unroll
        for (int k8 = 0; k8 < 8; k8++) {
            const int base = k8 * 8 + lk;
            const uint32_t* qh = smu + O_QHI + (m_base + lq4) * AST;
            const uint32_t* ql = smu + O_QLO + (m_base + lq4) * AST;
            uint32_t ah[4] = {qh[base], qh[base + 8 * AST], qh[base + 4], qh[base + 8 * AST + 4]};
            uint32_t al[4] = {ql[base], ql[base + 8 * AST], ql[base + 4], ql[base + 8 * AST + 4]};
#pragma unroll
            for (int nt = 0; nt < 16; nt++) {
                const uint32_t* kh = smu + O_KHI + (nt * 8 + lq4) * AST;
                const uint32_t* kl = smu + O_KLO + (nt * 8 + lq4) * AST;
                uint32_t bh[2] = {kh[base], kh[base + 4]};
                uint32_t bl[2] = {kl[base], kl[base + 4]};
                mma16(s_[nt], ah, bh);
                mma16(s_[nt], ah, bl);
                mma16(s_[nt], al, bh);
            }
        }

        // ---- causal mask (diagonal tile only: ks == q0) ----
        if (ks + 128 > q0) {
            const int q_lo = q0 + m_base + lq4, q_hi = q_lo + 8;
#pragma unroll
            for (int nt = 0; nt < 16; nt++) {
                const int key0 = ks + nt * 8 + 2 * lk;
                if (key0 > q_lo)     s_[nt][0] = -1e30f;
                if (key0 + 1 > q_lo) s_[nt][1] = -1e30f;
                if (key0 > q_hi)     s_[nt][2] = -1e30f;
                if (key0 + 1 > q_hi) s_[nt][3] = -1e30f;
            }
        }

        // ---- warp-local online softmax (log2 units) ----
        float mx0 = -1e30f, mx1 = -1e30f;
#pragma unroll
        for (int nt = 0; nt < 16; nt++) {
            mx0 = fmaxf(mx0, fmaxf(s_[nt][0], s_[nt][1]));
            mx1 = fmaxf(mx1, fmaxf(s_[nt][2], s_[nt][3]));
        }
        mx0 = fmaxf(mx0, __shfl_xor_sync(0xffffffffu, mx0, 1));
        mx0 = fmaxf(mx0, __shfl_xor_sync(0xffffffffu, mx0, 2));
        mx1 = fmaxf(mx1, __shfl_xor_sync(0xffffffffu, mx1, 1));
        mx1 = fmaxf(mx1, __shfl_xor_sync(0xffffffffu, mx1, 2));

        const float mn_lo = fmaxf(m_lo, mx0);
        const float mn_hi = fmaxf(m_hi, mx1);
        const float al_ = ex2f(m_lo - mn_lo);
        const float ah_ = ex2f(m_hi - mn_hi);
        m_lo = mn_lo; m_hi = mn_hi;

        // P in registers: overwrite s_[nt] with packed bf16 A-fragments
        // s_[nt][0]=Hpair(row lo), [1]=Hpair(row hi), [2]=Lpair(lo), [3]=Lpair(hi)
        float ps0 = 0.f, ps1 = 0.f;
#pragma unroll
        for (int nt = 0; nt < 16; nt++) {
            float p0 = ex2f(s_[nt][0] - mn_lo);
            float p1 = ex2f(s_[nt][1] - mn_lo);
            float p2 = ex2f(s_[nt][2] - mn_hi);
            float p3 = ex2f(s_[nt][3] - mn_hi);
            ps0 += p0 + p1;
            ps1 += p2 + p3;
            uint32_t h0, l0, h1, l1;
            split2(p0, p1, h0, l0);
            split2(p2, p3, h1, l1);
            s_[nt][0] = __uint_as_float(h0);
            s_[nt][1] = __uint_as_float(h1);
            s_[nt][2] = __uint_as_float(l0);
            s_[nt][3] = __uint_as_float(l1);
        }
        ps0 += __shfl_xor_sync(0xffffffffu, ps0, 1);
        ps0 += __shfl_xor_sync(0xffffffffu, ps0, 2);
        ps1 += __shfl_xor_sync(0xffffffffu, ps1, 1);
        ps1 += __shfl_xor_sync(0xffffffffu, ps1, 2);
        l_lo = l_lo * al_ + ps0;
        l_hi = l_hi * ah_ + ps1;
#pragma unroll
        for (int nd = 0; nd < 16; nd++) {
            o_[nd][0] *= al_; o_[nd][1] *= al_;
            o_[nd][2] *= ah_; o_[nd][3] *= ah_;
        }

        CPA_WAIT0();               // V_cur resident
        __syncthreads();           // + all warps done reading K
        if (!last) { loadK(ks + 128); CPA_COMMIT(); }

        // ---- O += P V : A from registers, B = Vt smem ----
#pragma unroll
        for (int kk = 0; kk < 8; kk++) {
            const int base = kk * 8 + lk;
            uint32_t pa_h[4] = {__float_as_uint(s_[2 * kk][0]), __float_as_uint(s_[2 * kk][1]),
                                __float_as_uint(s_[2 * kk + 1][0]), __float_as_uint(s_[2 * kk + 1][1])};
            uint32_t pa_l[4] = {__float_as_uint(s_[2 * kk][2]), __float_as_uint(s_[2 * kk][3]),
                                __float_as_uint(s_[2 * kk + 1][2]), __float_as_uint(s_[2 * kk + 1][3])};
#pragma unroll
            for (int nd = 0; nd < 16; nd++) {
                const uint32_t* vh = smu + O_VHI + (nd * 8 + lq4) * AST;
                const uint32_t* vl = smu + O_VLO + (nd * 8 + lq4) * AST;
                uint32_t bh[2] = {vh[base], vh[base + 4]};
                uint32_t bl[2] = {vl[base], vl[base + 4]};
                mma16(o_[nd], pa_h, bh);
                mma16(o_[nd], pa_h, bl);
                mma16(o_[nd], pa_l, bh);
            }
        }

        if (!last) {
            __syncthreads();       // all warps done reading V
            loadV(ks + 128);
            CPA_COMMIT();
        }
    }

    // ---- write partials ----
    const int pbase = ((b * 16 + qt) * 8 + chunk) * 128;
#pragma unroll
    for (int h = 0; h < 2; h++) {
        const int row = m_base + lq4 + 8 * h;
#pragma unroll
        for (int nd = 0; nd < 16; nd++) {
            const int col = nd * 8 + 2 * lk;
            *(float2*)&g_Op[(size_t)(pbase + row) * DH + col] =
                make_float2(o_[nd][2 * h], o_[nd][2 * h + 1]);
        }
    }
    if (lk == 0) {
        g_m[pbase + m_base + lq4]     = m_lo;
        g_l[pbase + m_base + lq4]     = l_lo;
        g_m[pbase + m_base + lq4 + 8] = m_hi;
        g_l[pbase + m_base + lq4 + 8] = l_hi;
    }
}

// ---------------------------------------------------------------------------
// Combine: grid (16 qt, 4 b, 4 rowgroups), 256 thr; thread = 16 d of one row.
// ---------------------------------------------------------------------------
__global__ __launch_bounds__(256) void attn_combine(float* __restrict__ out)
{
    const int qt = blockIdx.x, b = blockIdx.y;
    const int tid = threadIdx.x;
    const int q = blockIdx.z * 32 + (tid >> 3);
    const int d0 = (tid & 7) * 16;
    const int nch = (qt + 2) >> 1;               // 1..8
    const int base = (b * 16 + qt) * 8 * 128 + q;   // chunk stride = 128

    float mm[8];
    int cc[8];
#pragma unroll
    for (int c = 0; c < 8; c++) {
        cc[c] = (c < nch) ? c : (nch - 1);
        mm[c] = g_m[base + cc[c] * 128];
    }
    float M = -1e30f;
#pragma unroll
    for (int c = 0; c < 8; c++) M = fmaxf(M, mm[c]);
    float ww[8], L = 0.f;
#pragma unroll
    for (int c = 0; c < 8; c++) {
        ww[c] = (c < nch) ? ex2f(mm[c] - M) : 0.f;
        L += ww[c] * g_l[base + cc[c] * 128];
    }
    const float inv = 1.f / L;

    float* op = out + (size_t)(b * TSEQ + qt * 128 + q) * DH + d0;
#pragma unroll
    for (int d = 0; d < 16; d += 4) {
        float4 a = make_float4(0.f, 0.f, 0.f, 0.f);
#pragma unroll
        for (int c = 0; c < 8; c++) {
            const float4 v = *(const float4*)(g_Op + (size_t)(base + cc[c] * 128) * DH + d0 + d);
            a.x += ww[c] * v.x; a.y += ww[c] * v.y;
            a.z += ww[c] * v.z; a.w += ww[c] * v.w;
        }
        a.x *= inv; a.y *= inv; a.z *= inv; a.w *= inv;
        *(float4*)(op + d) = a;
    }
}

// ---------------------------------------------------------------------------
extern "C" void kernel_launch(void* const* d_in, const int* in_sizes, int n_in,
                              void* d_out, int out_size)
{
    const float* x     = (const float*)d_in[0];
    const float* Wq    = (const float*)d_in[1];
    const float* Wk    = (const float*)d_in[2];
    const float* Wv    = (const float*)d_in[3];
    const float* theta = (const float*)d_in[4];
    float* out = (float*)d_out;

    cudaFuncSetAttribute(qkv_mma, cudaFuncAttributeMaxDynamicSharedMemorySize, QKV_SMEM);
    cudaFuncSetAttribute(attn_part, cudaFuncAttributeMaxDynamicSharedMemorySize, AT_SMEM);

    rope_table<<<TSEQ, 128>>>(theta);
    convert_inputs<<<(NX8 + 3 * NW8) / 256, 256>>>(x, Wq, Wk, Wv);

    dim3 g1(NTOK / 64, 3);
    qkv_mma<<<g1, 256, QKV_SMEM>>>(0);

    attn_part<<<288, 256, AT_SMEM>>>(0);

    dim3 g3(16, 4, 4);
    attn_combine<<<g3, 256>>>(out);
}